// round 4
// baseline (speedup 1.0000x reference)
#include <cuda_runtime.h>
#include <math.h>

#define D    64
#define G5   320          // 5*D
#define NTH  320          // threads per block
#define NCT  80           // column-threads (80 * TC = 320 cols)
#define TC   4            // contiguous gate columns per thread
#define NCG  4            // cell groups per block
#define CG   4            // cells per group
#define CPB  16           // cells per block (NCG * CG)

// Scratch ping-pong buffers (allocation-free: __device__ globals).
__device__ float g_A_h[(1 << 18) * D];
__device__ float g_A_c[(1 << 18) * D];
__device__ float g_B_h[(1 << 17) * D];
__device__ float g_B_c[(1 << 17) * D];
// Per-level Fenwick representatives (last row of each level's INPUT), 19 levels.
__device__ float g_lvl_h[19 * D];
__device__ float g_lvl_c[19 * D];
// K-pair-interleaved merge weights: pair (k2, j) -> floats {W[2k2][j], W[2k2+1][j]}
__device__ __align__(16) float g_w2l[32 * G5 * 2];
__device__ __align__(16) float g_w2r[32 * G5 * 2];

__device__ __forceinline__ float sigf(float x) {
    return 1.0f / (1.0f + expf(-x));
}

__device__ __forceinline__ unsigned long long fma2(unsigned long long a,
                                                   unsigned long long b,
                                                   unsigned long long c) {
    unsigned long long d;
    asm("fma.rn.f32x2 %0, %1, %2, %3;" : "=l"(d) : "l"(a), "l"(b), "l"(c));
    return d;
}

__device__ __forceinline__ float2 unpack2(unsigned long long v) {
    float2 r;
    asm("mov.b64 {%0, %1}, %2;" : "=f"(r.x), "=f"(r.y) : "l"(v));
    return r;
}

// Interleave merge weights by k-pairs: one-time prep per launch.
__global__ void prep_w2(const float* __restrict__ Wl, const float* __restrict__ Wr)
{
    int idx = blockIdx.x * blockDim.x + threadIdx.x;
    if (idx < 32 * G5) {
        int k2 = idx / G5;
        int j  = idx % G5;
        float2* dl = reinterpret_cast<float2*>(g_w2l);
        float2* dr = reinterpret_cast<float2*>(g_w2r);
        dl[idx] = make_float2(Wl[(2 * k2) * G5 + j], Wl[(2 * k2 + 1) * G5 + j]);
        dr[idx] = make_float2(Wr[(2 * k2) * G5 + j], Wr[(2 * k2 + 1) * G5 + j]);
    }
}

// One block: 16 cells x 320 gate columns. Thread (cg, ct) computes columns
// [4*ct, 4*ct+4) for cells [cell0 + 4*cg, cell0 + 4*cg + 4) using packed
// f32x2 FMAs with even/odd-k partial sums.
__global__ __launch_bounds__(NTH, 2)
void merge_kernel(const float* __restrict__ hb, const float* __restrict__ cb,
                  int src_sel, int dst_sel,
                  const float* __restrict__ b,
                  int n_out, int level)
{
    const float* h_src = (src_sel == 0) ? hb : (src_sel == 1 ? g_A_h : g_B_h);
    const float* c_src = (src_sel == 0) ? cb : (src_sel == 1 ? g_A_c : g_B_c);
    float* h_dst = (dst_sel == 1) ? g_A_h : g_B_h;
    float* c_dst = (dst_sel == 1) ? g_A_c : g_B_c;

    // 20 KB buffer. Phase 1: first 8 KB = interleaved h-stage
    // (float4 per (cell,k2) = {hl[2k2], hl[2k2+1], hr[2k2], hr[2k2+1]}).
    // Phase 2 (h dead): full 20 KB = gate matrix [CPB][G5].
    __shared__ __align__(16) float s_buf[CPB * G5];

    const int tid   = threadIdx.x;
    const int cell0 = blockIdx.x * CPB;
    const int ct    = tid % NCT;
    const int cg    = tid / NCT;

    // ---- Stage h interleaved ----
    {
        const float4* src4 = reinterpret_cast<const float4*>(h_src) + (size_t)cell0 * 32;
        for (int idx = tid; idx < CPB * 2 * 16; idx += NTH) {
            int r  = idx >> 4;      // row within block's 32 input rows
            int f  = idx & 15;      // float4 within row (k = 4f..4f+3)
            int c  = r >> 1;
            int lr = r & 1;         // 0 = hl (lo half), 1 = hr (hi half)
            float4 v = make_float4(0.f, 0.f, 0.f, 0.f);
            if (cell0 + c < n_out) v = src4[idx];
            float2* p = reinterpret_cast<float2*>(s_buf + (c * 32 + 2 * f) * 4);
            p[lr]     = make_float2(v.x, v.y);   // k2 = 2f
            p[2 + lr] = make_float2(v.z, v.w);   // k2 = 2f+1
        }
    }
    __syncthreads();

    // ---- GEMM phase (packed over k-parity) ----
    const float* wl = g_w2l + 8 * ct;   // floats; pair (k2, 4ct..) at +k2*640
    const float* wr = g_w2r + 8 * ct;

    unsigned long long acc[CG][TC];
#pragma unroll
    for (int c = 0; c < CG; ++c)
#pragma unroll
        for (int j = 0; j < TC; ++j) acc[c][j] = 0ull;

    const ulonglong2* hbase =
        reinterpret_cast<const ulonglong2*>(s_buf) + (cg * CG) * 32;

#pragma unroll 4
    for (int k2 = 0; k2 < 32; ++k2) {
        ulonglong2 wla = *reinterpret_cast<const ulonglong2*>(wl + k2 * 640);
        ulonglong2 wlb = *reinterpret_cast<const ulonglong2*>(wl + k2 * 640 + 4);
        ulonglong2 wra = *reinterpret_cast<const ulonglong2*>(wr + k2 * 640);
        ulonglong2 wrb = *reinterpret_cast<const ulonglong2*>(wr + k2 * 640 + 4);
#pragma unroll
        for (int c = 0; c < CG; ++c) {
            ulonglong2 hv = hbase[c * 32 + k2];  // .x = hl pair, .y = hr pair
            acc[c][0] = fma2(wla.x, hv.x, acc[c][0]);
            acc[c][1] = fma2(wla.y, hv.x, acc[c][1]);
            acc[c][2] = fma2(wlb.x, hv.x, acc[c][2]);
            acc[c][3] = fma2(wlb.y, hv.x, acc[c][3]);
            acc[c][0] = fma2(wra.x, hv.y, acc[c][0]);
            acc[c][1] = fma2(wra.y, hv.y, acc[c][1]);
            acc[c][2] = fma2(wrb.x, hv.y, acc[c][2]);
            acc[c][3] = fma2(wrb.y, hv.y, acc[c][3]);
        }
    }
    __syncthreads();   // h-stage dead; buffer reusable as gate matrix

    // ---- Reduce k-parity partials, add bias, exchange through smem ----
    {
        float4 bb = reinterpret_cast<const float4*>(b)[ct];
#pragma unroll
        for (int c = 0; c < CG; ++c) {
            float2 p0 = unpack2(acc[c][0]);
            float2 p1 = unpack2(acc[c][1]);
            float2 p2 = unpack2(acc[c][2]);
            float2 p3 = unpack2(acc[c][3]);
            float4 g = make_float4(bb.x + p0.x + p0.y, bb.y + p1.x + p1.y,
                                   bb.z + p2.x + p2.y, bb.w + p3.x + p3.y);
            *reinterpret_cast<float4*>(s_buf + (cg * CG + c) * G5 + 4 * ct) = g;
        }
    }
    __syncthreads();

    // ---- Elementwise LSTM update. Gate order: i, o, u, fl, fr. ----
    for (int idx = tid; idx < CPB * D; idx += NTH) {
        int c = idx >> 6;
        int d = idx & 63;
        int cell = cell0 + c;
        if (cell < n_out) {
            const float* g = s_buf + c * G5;
            float gi  = g[0 * D + d];
            float go  = g[1 * D + d];
            float gu  = g[2 * D + d];
            float gfl = g[3 * D + d];
            float gfr = g[4 * D + d];
            float cl = c_src[(size_t)(2 * cell)     * D + d];
            float cr = c_src[(size_t)(2 * cell + 1) * D + d];
            float cc = sigf(gi) * tanhf(gu) + sigf(gfl) * cl + sigf(gfr) * cr;
            float hh = sigf(go) * tanhf(cc);
            c_dst[(size_t)cell * D + d] = cc;
            h_dst[(size_t)cell * D + d] = hh;
        }
    }

    // Fenwick representative: last row of this level's INPUT.
    if (blockIdx.x == 0 && tid < D) {
        int last = 2 * n_out - 1;
        g_lvl_h[level * D + tid] = h_src[(size_t)last * D + tid];
        g_lvl_c[level * D + tid] = c_src[(size_t)last * D + tid];
    }
}

// Single-block tail: remaining small levels (n_start <= 64, buffers only)
// plus the summary fold. Saves ~7 kernel launches of latency floor.
__global__ __launch_bounds__(NTH)
void tail_kernel(const float* __restrict__ mWl, const float* __restrict__ mWr,
                 const float* __restrict__ mb,
                 const float* __restrict__ sWl, const float* __restrict__ sWr,
                 const float* __restrict__ sb,
                 int n_start, int src_sel, int level_start, int n_lvls_total,
                 float* __restrict__ out)
{
    __shared__ float s_h[64 * D];     // 16 KB (level input h, n <= 64 rows)
    __shared__ float s_g[8 * G5];     // 10 KB (8 cells of gates)
    __shared__ float sh[D], sc2[D];

    const int tid = threadIdx.x;
    int n = n_start, src = src_sel, level = level_start;

    while (n > 1) {
        const float* h_src = (src == 1) ? g_A_h : g_B_h;
        const float* c_src = (src == 1) ? g_A_c : g_B_c;
        int dst = (level & 1) ? 2 : 1;
        float* h_dst = (dst == 1) ? g_A_h : g_B_h;
        float* c_dst = (dst == 1) ? g_A_c : g_B_c;

        // Fenwick representative = last row of this level's input.
        if (tid < D) {
            g_lvl_h[level * D + tid] = h_src[(n - 1) * D + tid];
            g_lvl_c[level * D + tid] = c_src[(n - 1) * D + tid];
        }
        // Stage input h.
        for (int i = tid; i < n * D; i += NTH) s_h[i] = h_src[i];
        __syncthreads();

        int n_out = n >> 1;
        for (int c0 = 0; c0 < n_out; c0 += 8) {
            float acc[8];
            float bv = mb[tid];
#pragma unroll
            for (int c = 0; c < 8; ++c) acc[c] = bv;
            for (int k = 0; k < D; ++k) {
                float wlv = mWl[k * G5 + tid];
                float wrv = mWr[k * G5 + tid];
#pragma unroll
                for (int c = 0; c < 8; ++c) {
                    int cell = c0 + c;
                    if (cell < n_out) {
                        acc[c] = fmaf(s_h[(2 * cell) * D + k], wlv, acc[c]);
                        acc[c] = fmaf(s_h[(2 * cell + 1) * D + k], wrv, acc[c]);
                    }
                }
            }
#pragma unroll
            for (int c = 0; c < 8; ++c) s_g[c * G5 + tid] = acc[c];
            __syncthreads();
            for (int idx = tid; idx < 8 * D; idx += NTH) {
                int c = idx >> 6;
                int d = idx & 63;
                int cell = c0 + c;
                if (cell < n_out) {
                    const float* g = s_g + c * G5;
                    float cc = sigf(g[d]) * tanhf(g[2 * D + d])
                             + sigf(g[3 * D + d]) * c_src[(2 * cell) * D + d]
                             + sigf(g[4 * D + d]) * c_src[(2 * cell + 1) * D + d];
                    float hh = sigf(g[D + d]) * tanhf(cc);
                    c_dst[cell * D + d] = cc;
                    h_dst[cell * D + d] = hh;
                }
            }
            __syncthreads();
        }
        n = n_out; src = dst; ++level;
    }

    // Summary fold over per-level representatives; root in buffer 'src'.
    {
        const float* rh = (src == 1) ? g_A_h : g_B_h;
        const float* rc = (src == 1) ? g_A_c : g_B_c;
        if (tid < D) { sh[tid] = rh[tid]; sc2[tid] = rc[tid]; }
        __syncthreads();

        for (int l = n_lvls_total - 1; l >= 0; --l) {
            const float* lh = g_lvl_h + l * D;
            float acc = sb[tid];
#pragma unroll 8
            for (int k = 0; k < D; ++k) {
                acc = fmaf(sh[k], sWl[k * G5 + tid], acc);
                acc = fmaf(lh[k], sWr[k * G5 + tid], acc);
            }
            s_g[tid] = acc;
            __syncthreads();
            if (tid < D) {
                const float* lc = g_lvl_c + l * D;
                float cc = sigf(s_g[tid]) * tanhf(s_g[2 * D + tid])
                         + sigf(s_g[3 * D + tid]) * sc2[tid]
                         + sigf(s_g[4 * D + tid]) * lc[tid];
                float hh = sigf(s_g[D + tid]) * tanhf(cc);
                sc2[tid] = cc;
                sh[tid] = hh;
            }
            __syncthreads();
        }
        if (tid < D) {
            out[tid]     = sh[tid];
            out[D + tid] = sc2[tid];
        }
    }
}

extern "C" void kernel_launch(void* const* d_in, const int* in_sizes, int n_in,
                              void* d_out, int out_size)
{
    const float* h_bot = (const float*)d_in[0];
    const float* c_bot = (const float*)d_in[1];
    const float* mWl   = (const float*)d_in[2];
    const float* mWr   = (const float*)d_in[3];
    const float* mb    = (const float*)d_in[4];
    const float* sWl   = (const float*)d_in[5];
    const float* sWr   = (const float*)d_in[6];
    const float* sb    = (const float*)d_in[7];

    prep_w2<<<(32 * G5 + 255) / 256, 256>>>(mWl, mWr);

    int n = in_sizes[0] / D;   // 524288 leaves
    int level = 0;
    int src_sel = 0;
    while (n > 64) {
        int n_out = n >> 1;
        int dst_sel = (level & 1) ? 2 : 1;
        int blocks = (n_out + CPB - 1) / CPB;
        merge_kernel<<<blocks, NTH>>>(h_bot, c_bot, src_sel, dst_sel,
                                      mb, n_out, level);
        src_sel = dst_sel;
        n = n_out;
        ++level;
    }
    // Total level count = levels done + log2(remaining n).
    int total = level;
    for (int m = n; m > 1; m >>= 1) ++total;
    tail_kernel<<<1, NTH>>>(mWl, mWr, mb, sWl, sWr, sb,
                            n, src_sel, level, total, (float*)d_out);
}

// round 5
// speedup vs baseline: 1.1562x; 1.1562x over previous
#include <cuda_runtime.h>
#include <math.h>

#define D    64
#define G5   320          // 5*D
#define NTH  320          // threads per block
#define NCT  160          // column-threads (160 * TC = 320 cols)
#define TC   2            // gate columns per thread
#define NCG  2            // cell groups per block
#define CG   16           // cells per group
#define CPB  32           // cells per block (NCG * CG)

// Scratch ping-pong buffers (allocation-free: __device__ globals).
__device__ float g_A_h[(1 << 18) * D];
__device__ float g_A_c[(1 << 18) * D];
__device__ float g_B_h[(1 << 17) * D];
__device__ float g_B_c[(1 << 17) * D];
// Per-level Fenwick representatives (last row of each level's INPUT), 19 levels.
__device__ float g_lvl_h[19 * D];
__device__ float g_lvl_c[19 * D];
// K-pair-interleaved merge weights: float2 at [k2*G5 + j] = {W[2k2][j], W[2k2+1][j]}
__device__ __align__(16) float g_w2l[32 * G5 * 2];
__device__ __align__(16) float g_w2r[32 * G5 * 2];

__device__ __forceinline__ float sigf(float x) {
    return 1.0f / (1.0f + expf(-x));
}

__device__ __forceinline__ unsigned long long fma2(unsigned long long a,
                                                   unsigned long long b,
                                                   unsigned long long c) {
    unsigned long long d;
    asm("fma.rn.f32x2 %0, %1, %2, %3;" : "=l"(d) : "l"(a), "l"(b), "l"(c));
    return d;
}

__device__ __forceinline__ float2 unpack2(unsigned long long v) {
    float2 r;
    asm("mov.b64 {%0, %1}, %2;" : "=f"(r.x), "=f"(r.y) : "l"(v));
    return r;
}

// Interleave merge weights by k-pairs: one-time prep per launch.
__global__ void prep_w2(const float* __restrict__ Wl, const float* __restrict__ Wr)
{
    int idx = blockIdx.x * blockDim.x + threadIdx.x;
    if (idx < 32 * G5) {
        int k2 = idx / G5;
        int j  = idx % G5;
        float2* dl = reinterpret_cast<float2*>(g_w2l);
        float2* dr = reinterpret_cast<float2*>(g_w2r);
        dl[idx] = make_float2(Wl[(2 * k2) * G5 + j], Wl[(2 * k2 + 1) * G5 + j]);
        dr[idx] = make_float2(Wr[(2 * k2) * G5 + j], Wr[(2 * k2 + 1) * G5 + j]);
    }
}

// One block: 32 cells x 320 gate columns. Thread (cg, ct) computes columns
// {2ct, 2ct+1} for cells [cell0 + 16*cg, cell0 + 16*cg + 16) using packed
// f32x2 FMAs with even/odd-k partial sums.
__global__ __launch_bounds__(NTH, 2)
void merge_kernel(const float* __restrict__ hb, const float* __restrict__ cb,
                  int src_sel, int dst_sel,
                  const float* __restrict__ b,
                  int n_out, int level)
{
    const float* h_src = (src_sel == 0) ? hb : (src_sel == 1 ? g_A_h : g_B_h);
    const float* c_src = (src_sel == 0) ? cb : (src_sel == 1 ? g_A_c : g_B_c);
    float* h_dst = (dst_sel == 1) ? g_A_h : g_B_h;
    float* c_dst = (dst_sel == 1) ? g_A_c : g_B_c;

    // 40 KB buffer. Phase 1: first 16 KB = interleaved h-stage
    // (float4 per (cell,k2) = {hl[2k2], hl[2k2+1], hr[2k2], hr[2k2+1]}).
    // Phase 2 (h dead): full 40 KB = gate matrix [CPB][G5].
    __shared__ __align__(16) float s_buf[CPB * G5];

    const int tid   = threadIdx.x;
    const int cell0 = blockIdx.x * CPB;
    const int ct    = tid % NCT;
    const int cg    = tid / NCT;

    // ---- Stage h interleaved ----
    {
        const float4* src4 = reinterpret_cast<const float4*>(h_src) + (size_t)cell0 * 32;
        for (int idx = tid; idx < CPB * 2 * 16; idx += NTH) {
            int r  = idx >> 4;      // row within block's 64 input rows
            int f  = idx & 15;      // float4 within row (k = 4f..4f+3)
            int c  = r >> 1;
            int lr = r & 1;         // 0 = hl, 1 = hr
            float4 v = make_float4(0.f, 0.f, 0.f, 0.f);
            if (cell0 + c < n_out) v = src4[idx];
            float2* p = reinterpret_cast<float2*>(s_buf + (c * 32 + 2 * f) * 4);
            p[lr]     = make_float2(v.x, v.y);   // k2 = 2f
            p[2 + lr] = make_float2(v.z, v.w);   // k2 = 2f+1
        }
    }
    __syncthreads();

    // ---- GEMM phase (packed over k-parity) ----
    // Thread's weight cols {2ct, 2ct+1}: bytes k2*2560 + ct*16 in g_w2*.
    const char* wl = reinterpret_cast<const char*>(g_w2l) + 16 * ct;
    const char* wr = reinterpret_cast<const char*>(g_w2r) + 16 * ct;

    unsigned long long acc[CG][TC];
#pragma unroll
    for (int c = 0; c < CG; ++c) {
        acc[c][0] = 0ull;
        acc[c][1] = 0ull;
    }

    const ulonglong2* hbase =
        reinterpret_cast<const ulonglong2*>(s_buf) + (cg * CG) * 32;

#pragma unroll 2
    for (int k2 = 0; k2 < 32; ++k2) {
        // wla.x = col 2ct k-pair, wla.y = col 2ct+1 k-pair (same for wra)
        ulonglong2 wla = *reinterpret_cast<const ulonglong2*>(wl + k2 * 2560);
        ulonglong2 wra = *reinterpret_cast<const ulonglong2*>(wr + k2 * 2560);
#pragma unroll
        for (int c = 0; c < CG; ++c) {
            ulonglong2 hv = hbase[c * 32 + k2];  // .x = hl pair, .y = hr pair
            acc[c][0] = fma2(wla.x, hv.x, acc[c][0]);
            acc[c][1] = fma2(wla.y, hv.x, acc[c][1]);
            acc[c][0] = fma2(wra.x, hv.y, acc[c][0]);
            acc[c][1] = fma2(wra.y, hv.y, acc[c][1]);
        }
    }
    __syncthreads();   // h-stage dead; buffer reusable as gate matrix

    // ---- Reduce k-parity partials, add bias, exchange through smem ----
    {
        float2 bb = reinterpret_cast<const float2*>(b)[ct];
#pragma unroll
        for (int c = 0; c < CG; ++c) {
            float2 p0 = unpack2(acc[c][0]);
            float2 p1 = unpack2(acc[c][1]);
            float2 g = make_float2(bb.x + p0.x + p0.y, bb.y + p1.x + p1.y);
            *reinterpret_cast<float2*>(s_buf + (cg * CG + c) * G5 + 2 * ct) = g;
        }
    }
    __syncthreads();

    // ---- Elementwise LSTM update. Gate order: i, o, u, fl, fr. ----
    for (int idx = tid; idx < CPB * D; idx += NTH) {
        int c = idx >> 6;
        int d = idx & 63;
        int cell = cell0 + c;
        if (cell < n_out) {
            const float* g = s_buf + c * G5;
            float gi  = g[0 * D + d];
            float go  = g[1 * D + d];
            float gu  = g[2 * D + d];
            float gfl = g[3 * D + d];
            float gfr = g[4 * D + d];
            float cl = c_src[(size_t)(2 * cell)     * D + d];
            float cr = c_src[(size_t)(2 * cell + 1) * D + d];
            float cc = sigf(gi) * tanhf(gu) + sigf(gfl) * cl + sigf(gfr) * cr;
            float hh = sigf(go) * tanhf(cc);
            c_dst[(size_t)cell * D + d] = cc;
            h_dst[(size_t)cell * D + d] = hh;
        }
    }

    // Fenwick representative: last row of this level's INPUT.
    if (blockIdx.x == 0 && tid < D) {
        int last = 2 * n_out - 1;
        g_lvl_h[level * D + tid] = h_src[(size_t)last * D + tid];
        g_lvl_c[level * D + tid] = c_src[(size_t)last * D + tid];
    }
}

// Single-block tail: remaining small levels (n_start <= 64, buffers only)
// plus the summary fold. Saves ~7 kernel launches of latency floor.
__global__ __launch_bounds__(NTH)
void tail_kernel(const float* __restrict__ mWl, const float* __restrict__ mWr,
                 const float* __restrict__ mb,
                 const float* __restrict__ sWl, const float* __restrict__ sWr,
                 const float* __restrict__ sb,
                 int n_start, int src_sel, int level_start, int n_lvls_total,
                 float* __restrict__ out)
{
    __shared__ float s_h[64 * D];     // 16 KB (level input h, n <= 64 rows)
    __shared__ float s_g[8 * G5];     // 10 KB (8 cells of gates)
    __shared__ float sh[D], sc2[D];

    const int tid = threadIdx.x;
    int n = n_start, src = src_sel, level = level_start;

    while (n > 1) {
        const float* h_src = (src == 1) ? g_A_h : g_B_h;
        const float* c_src = (src == 1) ? g_A_c : g_B_c;
        int dst = (level & 1) ? 2 : 1;
        float* h_dst = (dst == 1) ? g_A_h : g_B_h;
        float* c_dst = (dst == 1) ? g_A_c : g_B_c;

        // Fenwick representative = last row of this level's input.
        if (tid < D) {
            g_lvl_h[level * D + tid] = h_src[(n - 1) * D + tid];
            g_lvl_c[level * D + tid] = c_src[(n - 1) * D + tid];
        }
        // Stage input h.
        for (int i = tid; i < n * D; i += NTH) s_h[i] = h_src[i];
        __syncthreads();

        int n_out = n >> 1;
        for (int c0 = 0; c0 < n_out; c0 += 8) {
            float acc[8];
            float bv = mb[tid];
#pragma unroll
            for (int c = 0; c < 8; ++c) acc[c] = bv;
            for (int k = 0; k < D; ++k) {
                float wlv = mWl[k * G5 + tid];
                float wrv = mWr[k * G5 + tid];
#pragma unroll
                for (int c = 0; c < 8; ++c) {
                    int cell = c0 + c;
                    if (cell < n_out) {
                        acc[c] = fmaf(s_h[(2 * cell) * D + k], wlv, acc[c]);
                        acc[c] = fmaf(s_h[(2 * cell + 1) * D + k], wrv, acc[c]);
                    }
                }
            }
#pragma unroll
            for (int c = 0; c < 8; ++c) s_g[c * G5 + tid] = acc[c];
            __syncthreads();
            for (int idx = tid; idx < 8 * D; idx += NTH) {
                int c = idx >> 6;
                int d = idx & 63;
                int cell = c0 + c;
                if (cell < n_out) {
                    const float* g = s_g + c * G5;
                    float cc = sigf(g[d]) * tanhf(g[2 * D + d])
                             + sigf(g[3 * D + d]) * c_src[(2 * cell) * D + d]
                             + sigf(g[4 * D + d]) * c_src[(2 * cell + 1) * D + d];
                    float hh = sigf(g[D + d]) * tanhf(cc);
                    c_dst[cell * D + d] = cc;
                    h_dst[cell * D + d] = hh;
                }
            }
            __syncthreads();
        }
        n = n_out; src = dst; ++level;
    }

    // Summary fold over per-level representatives; root in buffer 'src'.
    {
        const float* rh = (src == 1) ? g_A_h : g_B_h;
        const float* rc = (src == 1) ? g_A_c : g_B_c;
        if (tid < D) { sh[tid] = rh[tid]; sc2[tid] = rc[tid]; }
        __syncthreads();

        for (int l = n_lvls_total - 1; l >= 0; --l) {
            const float* lh = g_lvl_h + l * D;
            float acc = sb[tid];
#pragma unroll 8
            for (int k = 0; k < D; ++k) {
                acc = fmaf(sh[k], sWl[k * G5 + tid], acc);
                acc = fmaf(lh[k], sWr[k * G5 + tid], acc);
            }
            s_g[tid] = acc;
            __syncthreads();
            if (tid < D) {
                const float* lc = g_lvl_c + l * D;
                float cc = sigf(s_g[tid]) * tanhf(s_g[2 * D + tid])
                         + sigf(s_g[3 * D + tid]) * sc2[tid]
                         + sigf(s_g[4 * D + tid]) * lc[tid];
                float hh = sigf(s_g[D + tid]) * tanhf(cc);
                sc2[tid] = cc;
                sh[tid] = hh;
            }
            __syncthreads();
        }
        if (tid < D) {
            out[tid]     = sh[tid];
            out[D + tid] = sc2[tid];
        }
    }
}

extern "C" void kernel_launch(void* const* d_in, const int* in_sizes, int n_in,
                              void* d_out, int out_size)
{
    const float* h_bot = (const float*)d_in[0];
    const float* c_bot = (const float*)d_in[1];
    const float* mWl   = (const float*)d_in[2];
    const float* mWr   = (const float*)d_in[3];
    const float* mb    = (const float*)d_in[4];
    const float* sWl   = (const float*)d_in[5];
    const float* sWr   = (const float*)d_in[6];
    const float* sb    = (const float*)d_in[7];

    prep_w2<<<(32 * G5 + 255) / 256, 256>>>(mWl, mWr);

    int n = in_sizes[0] / D;   // 524288 leaves
    int level = 0;
    int src_sel = 0;
    while (n > 64) {
        int n_out = n >> 1;
        int dst_sel = (level & 1) ? 2 : 1;
        int blocks = (n_out + CPB - 1) / CPB;
        merge_kernel<<<blocks, NTH>>>(h_bot, c_bot, src_sel, dst_sel,
                                      mb, n_out, level);
        src_sel = dst_sel;
        n = n_out;
        ++level;
    }
    // Total level count = levels done + log2(remaining n).
    int total = level;
    for (int m = n; m > 1; m >>= 1) ++total;
    tail_kernel<<<1, NTH>>>(mWl, mWr, mb, sWl, sWr, sb,
                            n, src_sel, level, total, (float*)d_out);
}

// round 6
// speedup vs baseline: 1.2388x; 1.0714x over previous
#include <cuda_runtime.h>
#include <math.h>

#define D    64
#define G5   320          // 5*D
#define NTH  320          // threads per block
#define NCT  80           // column-threads (80 * TC = 320 cols)
#define TC   4            // gate columns per thread (2 packed col-pairs)
#define NCG  4            // cell groups per block
#define CG   8            // cells per group
#define CPB  32           // cells per block (NCG * CG)

// Scratch ping-pong buffers (allocation-free: __device__ globals).
__device__ float g_A_h[(1 << 18) * D];
__device__ float g_A_c[(1 << 18) * D];
__device__ float g_B_h[(1 << 17) * D];
__device__ float g_B_c[(1 << 17) * D];
// Per-level Fenwick representatives (last row of each level's INPUT), 19 levels.
__device__ float g_lvl_h[19 * D];
__device__ float g_lvl_c[19 * D];

__device__ __forceinline__ float sigf(float x) {
    return 1.0f / (1.0f + expf(-x));
}

__device__ __forceinline__ unsigned long long fma2(unsigned long long a,
                                                   unsigned long long b,
                                                   unsigned long long c) {
    unsigned long long d;
    asm("fma.rn.f32x2 %0, %1, %2, %3;" : "=l"(d) : "l"(a), "l"(b), "l"(c));
    return d;
}

__device__ __forceinline__ float2 unpack2(unsigned long long v) {
    float2 r;
    asm("mov.b64 {%0, %1}, %2;" : "=f"(r.x), "=f"(r.y) : "l"(v));
    return r;
}

// One block: 32 cells x 320 gate columns. Thread (cg, ct) computes packed
// column pairs {4ct,4ct+1} and {4ct+2,4ct+3} for cells
// [cell0 + 8*cg, cell0 + 8*cg + 8). Weights load straight from row-major
// Wl/Wr (LDG.128 = 2 f32x2 col-pair operands); h is staged duplicated in
// smem so one broadcast LDS.128 = {hl,hl,hr,hr} = 2 ready f32x2 operands.
__global__ __launch_bounds__(NTH, 2)
void merge_kernel(const float* __restrict__ hb, const float* __restrict__ cb,
                  int src_sel, int dst_sel,
                  const float* __restrict__ Wl, const float* __restrict__ Wr,
                  const float* __restrict__ b,
                  int n_out, int level)
{
    const float* h_src = (src_sel == 0) ? hb : (src_sel == 1 ? g_A_h : g_B_h);
    const float* c_src = (src_sel == 0) ? cb : (src_sel == 1 ? g_A_c : g_B_c);
    float* h_dst = (dst_sel == 1) ? g_A_h : g_B_h;
    float* c_dst = (dst_sel == 1) ? g_A_c : g_B_c;

    // 40 KB buffer. Phase 1: first 32 KB = duplicated h-stage
    // (float4 per (cell,k) = {hl[k], hl[k], hr[k], hr[k]}).
    // Phase 2 (h dead): full 40 KB = gate matrix [CPB][G5].
    __shared__ __align__(16) float s_buf[CPB * G5];

    const int tid   = threadIdx.x;
    const int cell0 = blockIdx.x * CPB;
    const int ct    = tid % NCT;
    const int cg    = tid / NCT;

    // ---- Stage h duplicated: s_h4[c*64 + k] = {hl,hl,hr,hr} ----
    {
        const float4* src4 = reinterpret_cast<const float4*>(h_src) + (size_t)cell0 * 32;
        for (int idx = tid; idx < CPB * 2 * 16; idx += NTH) {
            int r  = idx >> 4;      // row within block's 64 input rows
            int f  = idx & 15;      // float4 within row (k = 4f..4f+3)
            int c  = r >> 1;
            int lr = r & 1;         // 0 = hl (low float2), 1 = hr (high float2)
            float4 v = make_float4(0.f, 0.f, 0.f, 0.f);
            if (cell0 + c < n_out) v = src4[idx];
            float2* p = reinterpret_cast<float2*>(s_buf) + (c * 64 + 4 * f) * 2 + lr;
            p[0] = make_float2(v.x, v.x);
            p[2] = make_float2(v.y, v.y);
            p[4] = make_float2(v.z, v.z);
            p[6] = make_float2(v.w, v.w);
        }
    }
    __syncthreads();

    // ---- GEMM phase (packed over column pairs) ----
    unsigned long long acc[CG][2];
#pragma unroll
    for (int c = 0; c < CG; ++c) {
        acc[c][0] = 0ull;
        acc[c][1] = 0ull;
    }

    const float* wlp = Wl + 4 * ct;
    const float* wrp = Wr + 4 * ct;
    const ulonglong2* hbase =
        reinterpret_cast<const ulonglong2*>(s_buf) + (cg * CG) * 64;

#pragma unroll 2
    for (int k = 0; k < D; ++k) {
        // .x = f32x2 {W[k][4ct],W[k][4ct+1]}, .y = {W[k][4ct+2],W[k][4ct+3]}
        ulonglong2 wl = *reinterpret_cast<const ulonglong2*>(wlp + k * G5);
        ulonglong2 wr = *reinterpret_cast<const ulonglong2*>(wrp + k * G5);
#pragma unroll
        for (int c = 0; c < CG; ++c) {
            ulonglong2 hv = hbase[c * 64 + k];  // .x = {hl,hl}, .y = {hr,hr}
            acc[c][0] = fma2(wl.x, hv.x, acc[c][0]);
            acc[c][1] = fma2(wl.y, hv.x, acc[c][1]);
            acc[c][0] = fma2(wr.x, hv.y, acc[c][0]);
            acc[c][1] = fma2(wr.y, hv.y, acc[c][1]);
        }
    }
    __syncthreads();   // h-stage dead; buffer reusable as gate matrix

    // ---- Unpack, add bias, exchange through smem ----
    {
        float4 bb = reinterpret_cast<const float4*>(b)[ct];
#pragma unroll
        for (int c = 0; c < CG; ++c) {
            float2 p01 = unpack2(acc[c][0]);
            float2 p23 = unpack2(acc[c][1]);
            float4 g = make_float4(bb.x + p01.x, bb.y + p01.y,
                                   bb.z + p23.x, bb.w + p23.y);
            *reinterpret_cast<float4*>(s_buf + (cg * CG + c) * G5 + 4 * ct) = g;
        }
    }
    __syncthreads();

    // ---- Elementwise LSTM update. Gate order: i, o, u, fl, fr. ----
    for (int idx = tid; idx < CPB * D; idx += NTH) {
        int c = idx >> 6;
        int d = idx & 63;
        int cell = cell0 + c;
        if (cell < n_out) {
            const float* g = s_buf + c * G5;
            float gi  = g[0 * D + d];
            float go  = g[1 * D + d];
            float gu  = g[2 * D + d];
            float gfl = g[3 * D + d];
            float gfr = g[4 * D + d];
            float cl = c_src[(size_t)(2 * cell)     * D + d];
            float cr = c_src[(size_t)(2 * cell + 1) * D + d];
            float cc = sigf(gi) * tanhf(gu) + sigf(gfl) * cl + sigf(gfr) * cr;
            float hh = sigf(go) * tanhf(cc);
            c_dst[(size_t)cell * D + d] = cc;
            h_dst[(size_t)cell * D + d] = hh;
        }
    }

    // Fenwick representative: last row of this level's INPUT.
    if (blockIdx.x == 0 && tid < D) {
        int last = 2 * n_out - 1;
        g_lvl_h[level * D + tid] = h_src[(size_t)last * D + tid];
        g_lvl_c[level * D + tid] = c_src[(size_t)last * D + tid];
    }
}

// Single-block tail: remaining small levels (n_start <= 64, buffers only)
// plus the summary fold. Saves ~7 kernel launches of latency floor.
__global__ __launch_bounds__(NTH)
void tail_kernel(const float* __restrict__ mWl, const float* __restrict__ mWr,
                 const float* __restrict__ mb,
                 const float* __restrict__ sWl, const float* __restrict__ sWr,
                 const float* __restrict__ sb,
                 int n_start, int src_sel, int level_start, int n_lvls_total,
                 float* __restrict__ out)
{
    __shared__ float s_h[64 * D];     // 16 KB (level input h, n <= 64 rows)
    __shared__ float s_g[8 * G5];     // 10 KB (8 cells of gates)
    __shared__ float sh[D], sc2[D];

    const int tid = threadIdx.x;
    int n = n_start, src = src_sel, level = level_start;

    while (n > 1) {
        const float* h_src = (src == 1) ? g_A_h : g_B_h;
        const float* c_src = (src == 1) ? g_A_c : g_B_c;
        int dst = (level & 1) ? 2 : 1;
        float* h_dst = (dst == 1) ? g_A_h : g_B_h;
        float* c_dst = (dst == 1) ? g_A_c : g_B_c;

        // Fenwick representative = last row of this level's input.
        if (tid < D) {
            g_lvl_h[level * D + tid] = h_src[(n - 1) * D + tid];
            g_lvl_c[level * D + tid] = c_src[(n - 1) * D + tid];
        }
        // Stage input h.
        for (int i = tid; i < n * D; i += NTH) s_h[i] = h_src[i];
        __syncthreads();

        int n_out = n >> 1;
        for (int c0 = 0; c0 < n_out; c0 += 8) {
            float acc[8];
            float bv = mb[tid];
#pragma unroll
            for (int c = 0; c < 8; ++c) acc[c] = bv;
            for (int k = 0; k < D; ++k) {
                float wlv = mWl[k * G5 + tid];
                float wrv = mWr[k * G5 + tid];
#pragma unroll
                for (int c = 0; c < 8; ++c) {
                    int cell = c0 + c;
                    if (cell < n_out) {
                        acc[c] = fmaf(s_h[(2 * cell) * D + k], wlv, acc[c]);
                        acc[c] = fmaf(s_h[(2 * cell + 1) * D + k], wrv, acc[c]);
                    }
                }
            }
#pragma unroll
            for (int c = 0; c < 8; ++c) s_g[c * G5 + tid] = acc[c];
            __syncthreads();
            for (int idx = tid; idx < 8 * D; idx += NTH) {
                int c = idx >> 6;
                int d = idx & 63;
                int cell = c0 + c;
                if (cell < n_out) {
                    const float* g = s_g + c * G5;
                    float cc = sigf(g[d]) * tanhf(g[2 * D + d])
                             + sigf(g[3 * D + d]) * c_src[(2 * cell) * D + d]
                             + sigf(g[4 * D + d]) * c_src[(2 * cell + 1) * D + d];
                    float hh = sigf(g[D + d]) * tanhf(cc);
                    c_dst[cell * D + d] = cc;
                    h_dst[cell * D + d] = hh;
                }
            }
            __syncthreads();
        }
        n = n_out; src = dst; ++level;
    }

    // Summary fold over per-level representatives; root in buffer 'src'.
    {
        const float* rh = (src == 1) ? g_A_h : g_B_h;
        const float* rc = (src == 1) ? g_A_c : g_B_c;
        if (tid < D) { sh[tid] = rh[tid]; sc2[tid] = rc[tid]; }
        __syncthreads();

        for (int l = n_lvls_total - 1; l >= 0; --l) {
            const float* lh = g_lvl_h + l * D;
            float acc = sb[tid];
#pragma unroll 8
            for (int k = 0; k < D; ++k) {
                acc = fmaf(sh[k], sWl[k * G5 + tid], acc);
                acc = fmaf(lh[k], sWr[k * G5 + tid], acc);
            }
            s_g[tid] = acc;
            __syncthreads();
            if (tid < D) {
                const float* lc = g_lvl_c + l * D;
                float cc = sigf(s_g[tid]) * tanhf(s_g[2 * D + tid])
                         + sigf(s_g[3 * D + tid]) * sc2[tid]
                         + sigf(s_g[4 * D + tid]) * lc[tid];
                float hh = sigf(s_g[D + tid]) * tanhf(cc);
                sc2[tid] = cc;
                sh[tid] = hh;
            }
            __syncthreads();
        }
        if (tid < D) {
            out[tid]     = sh[tid];
            out[D + tid] = sc2[tid];
        }
    }
}

extern "C" void kernel_launch(void* const* d_in, const int* in_sizes, int n_in,
                              void* d_out, int out_size)
{
    const float* h_bot = (const float*)d_in[0];
    const float* c_bot = (const float*)d_in[1];
    const float* mWl   = (const float*)d_in[2];
    const float* mWr   = (const float*)d_in[3];
    const float* mb    = (const float*)d_in[4];
    const float* sWl   = (const float*)d_in[5];
    const float* sWr   = (const float*)d_in[6];
    const float* sb    = (const float*)d_in[7];

    int n = in_sizes[0] / D;   // 524288 leaves
    int level = 0;
    int src_sel = 0;
    while (n > 64) {
        int n_out = n >> 1;
        int dst_sel = (level & 1) ? 2 : 1;
        int blocks = (n_out + CPB - 1) / CPB;
        merge_kernel<<<blocks, NTH>>>(h_bot, c_bot, src_sel, dst_sel,
                                      mWl, mWr, mb, n_out, level);
        src_sel = dst_sel;
        n = n_out;
        ++level;
    }
    // Total level count = levels done + log2(remaining n).
    int total = level;
    for (int m = n; m > 1; m >>= 1) ++total;
    tail_kernel<<<1, NTH>>>(mWl, mWr, mb, sWl, sWr, sb,
                            n, src_sel, level, total, (float*)d_out);
}

// round 7
// speedup vs baseline: 1.3749x; 1.1098x over previous
#include <cuda_runtime.h>
#include <math.h>

#define D    64
#define G5   320          // 5*D
#define NTH  320          // threads per block
#define NCT  80           // column-threads (80 * TC = 320 cols)
#define TC   4            // contiguous gate columns per thread
#define NCG  4            // cell groups per block
#define CG   8            // cells per group
#define CPB  32           // cells per block (NCG * CG)

// Scratch ping-pong buffers (allocation-free: __device__ globals).
__device__ float g_A_h[(1 << 18) * D];
__device__ float g_A_c[(1 << 18) * D];
__device__ float g_B_h[(1 << 17) * D];
__device__ float g_B_c[(1 << 17) * D];
// Per-level Fenwick representatives (last row of each level's INPUT), 19 levels.
__device__ float g_lvl_h[19 * D];
__device__ float g_lvl_c[19 * D];

__device__ __forceinline__ float sigf(float x) {
    return 1.0f / (1.0f + expf(-x));
}

// One block: 32 cells x 320 gate columns. Thread (cg, ct) computes columns
// [4*ct, 4*ct+4) for cells [cell0 + 8*cg, cell0 + 8*cg + 8).
// Scalar FFMA version (proven best mix); occupancy raised to 3 blocks/SM.
__global__ __launch_bounds__(NTH, 3)
void merge_kernel(const float* __restrict__ hb, const float* __restrict__ cb,
                  int src_sel, int dst_sel,
                  const float* __restrict__ Wl, const float* __restrict__ Wr,
                  const float* __restrict__ b,
                  int n_out, int level)
{
    const float* h_src = (src_sel == 0) ? hb : (src_sel == 1 ? g_A_h : g_B_h);
    const float* c_src = (src_sel == 0) ? cb : (src_sel == 1 ? g_A_c : g_B_c);
    float* h_dst = (dst_sel == 1) ? g_A_h : g_B_h;
    float* c_dst = (dst_sel == 1) ? g_A_c : g_B_c;

    // 40 KB buffer. Phase 1: first 16 KB = interleaved h-stage.
    // Phase 2 (after h is dead): full 40 KB = gate matrix [CPB][G5].
    __shared__ __align__(16) float s_buf[CPB * G5];

    const int tid   = threadIdx.x;
    const int cell0 = blockIdx.x * CPB;
    const int ct    = tid % NCT;
    const int cg    = tid / NCT;

    // ---- Stage h interleaved: float4 at s_h2[c] + 4*k2 holds
    //      {hl[2k2], hr[2k2], hl[2k2+1], hr[2k2+1]} ----
    float* s_h2 = s_buf;
    {
        const float4* src4 = reinterpret_cast<const float4*>(h_src) + (size_t)cell0 * 32;
        for (int idx = tid; idx < CPB * 2 * 16; idx += NTH) {
            int r  = idx >> 4;      // row within block's 64 input rows
            int f4 = idx & 15;
            int c  = r >> 1;
            int lr = r & 1;
            float4 v = make_float4(0.f, 0.f, 0.f, 0.f);
            if (cell0 + c < n_out) v = src4[idx];
            float* dst = s_h2 + c * 128 + 8 * f4 + lr;
            dst[0] = v.x; dst[2] = v.y; dst[4] = v.z; dst[6] = v.w;
        }
    }
    __syncthreads();

    // ---- GEMM phase: acc[c][j] = b + sum_k hl*Wl + hr*Wr ----
    const float4* wl4 = reinterpret_cast<const float4*>(Wl);  // [k*80 + col4]
    const float4* wr4 = reinterpret_cast<const float4*>(Wr);
    float4 b4 = reinterpret_cast<const float4*>(b)[ct];

    float acc[CG][TC];
#pragma unroll
    for (int c = 0; c < CG; ++c) {
        acc[c][0] = b4.x; acc[c][1] = b4.y; acc[c][2] = b4.z; acc[c][3] = b4.w;
    }

    const float4* hbase = reinterpret_cast<const float4*>(s_h2) + (cg * CG) * 32;

#pragma unroll 2
    for (int k2 = 0; k2 < 32; ++k2) {
        float4 wl0 = wl4[(2 * k2    ) * NCT + ct];
        float4 wr0 = wr4[(2 * k2    ) * NCT + ct];
        float4 wl1 = wl4[(2 * k2 + 1) * NCT + ct];
        float4 wr1 = wr4[(2 * k2 + 1) * NCT + ct];
#pragma unroll
        for (int c = 0; c < CG; ++c) {
            float4 hv = hbase[c * 32 + k2];   // {hl[2k2], hr[2k2], hl[2k2+1], hr[2k2+1]}
            float a0 = acc[c][0], a1 = acc[c][1], a2 = acc[c][2], a3 = acc[c][3];
            a0 = fmaf(wl0.x, hv.x, a0); a1 = fmaf(wl0.y, hv.x, a1);
            a2 = fmaf(wl0.z, hv.x, a2); a3 = fmaf(wl0.w, hv.x, a3);
            a0 = fmaf(wr0.x, hv.y, a0); a1 = fmaf(wr0.y, hv.y, a1);
            a2 = fmaf(wr0.z, hv.y, a2); a3 = fmaf(wr0.w, hv.y, a3);
            a0 = fmaf(wl1.x, hv.z, a0); a1 = fmaf(wl1.y, hv.z, a1);
            a2 = fmaf(wl1.z, hv.z, a2); a3 = fmaf(wl1.w, hv.z, a3);
            a0 = fmaf(wr1.x, hv.w, a0); a1 = fmaf(wr1.y, hv.w, a1);
            a2 = fmaf(wr1.z, hv.w, a2); a3 = fmaf(wr1.w, hv.w, a3);
            acc[c][0] = a0; acc[c][1] = a1; acc[c][2] = a2; acc[c][3] = a3;
        }
    }
    __syncthreads();   // everyone done reading s_h2; buffer is reusable

    // ---- Exchange gates through smem ----
#pragma unroll
    for (int c = 0; c < CG; ++c) {
        float4* p = reinterpret_cast<float4*>(s_buf + (cg * CG + c) * G5) + ct;
        *p = make_float4(acc[c][0], acc[c][1], acc[c][2], acc[c][3]);
    }
    __syncthreads();

    // ---- Elementwise LSTM update. Gate order: i, o, u, fl, fr. ----
    for (int idx = tid; idx < CPB * D; idx += NTH) {
        int c = idx >> 6;
        int d = idx & 63;
        int cell = cell0 + c;
        if (cell < n_out) {
            const float* g = s_buf + c * G5;
            float gi  = g[0 * D + d];
            float go  = g[1 * D + d];
            float gu  = g[2 * D + d];
            float gfl = g[3 * D + d];
            float gfr = g[4 * D + d];
            float cl = c_src[(size_t)(2 * cell)     * D + d];
            float cr = c_src[(size_t)(2 * cell + 1) * D + d];
            float cc = sigf(gi) * tanhf(gu) + sigf(gfl) * cl + sigf(gfr) * cr;
            float hh = sigf(go) * tanhf(cc);
            c_dst[(size_t)cell * D + d] = cc;
            h_dst[(size_t)cell * D + d] = hh;
        }
    }

    // Fenwick representative: last row of this level's INPUT.
    if (blockIdx.x == 0 && tid < D) {
        int last = 2 * n_out - 1;
        g_lvl_h[level * D + tid] = h_src[(size_t)last * D + tid];
        g_lvl_c[level * D + tid] = c_src[(size_t)last * D + tid];
    }
}

// Single-block tail: remaining small levels (n_start <= 64, buffers only)
// plus the summary fold. Saves ~7 kernel launches of latency floor.
__global__ __launch_bounds__(NTH)
void tail_kernel(const float* __restrict__ mWl, const float* __restrict__ mWr,
                 const float* __restrict__ mb,
                 const float* __restrict__ sWl, const float* __restrict__ sWr,
                 const float* __restrict__ sb,
                 int n_start, int src_sel, int level_start, int n_lvls_total,
                 float* __restrict__ out)
{
    __shared__ float s_h[64 * D];     // 16 KB (level input h, n <= 64 rows)
    __shared__ float s_g[8 * G5];     // 10 KB (8 cells of gates)
    __shared__ float sh[D], sc2[D];

    const int tid = threadIdx.x;
    int n = n_start, src = src_sel, level = level_start;

    while (n > 1) {
        const float* h_src = (src == 1) ? g_A_h : g_B_h;
        const float* c_src = (src == 1) ? g_A_c : g_B_c;
        int dst = (level & 1) ? 2 : 1;
        float* h_dst = (dst == 1) ? g_A_h : g_B_h;
        float* c_dst = (dst == 1) ? g_A_c : g_B_c;

        // Fenwick representative = last row of this level's input.
        if (tid < D) {
            g_lvl_h[level * D + tid] = h_src[(n - 1) * D + tid];
            g_lvl_c[level * D + tid] = c_src[(n - 1) * D + tid];
        }
        // Stage input h.
        for (int i = tid; i < n * D; i += NTH) s_h[i] = h_src[i];
        __syncthreads();

        int n_out = n >> 1;
        for (int c0 = 0; c0 < n_out; c0 += 8) {
            float acc[8];
            float bv = mb[tid];
#pragma unroll
            for (int c = 0; c < 8; ++c) acc[c] = bv;
            for (int k = 0; k < D; ++k) {
                float wlv = mWl[k * G5 + tid];
                float wrv = mWr[k * G5 + tid];
#pragma unroll
                for (int c = 0; c < 8; ++c) {
                    int cell = c0 + c;
                    if (cell < n_out) {
                        acc[c] = fmaf(s_h[(2 * cell) * D + k], wlv, acc[c]);
                        acc[c] = fmaf(s_h[(2 * cell + 1) * D + k], wrv, acc[c]);
                    }
                }
            }
#pragma unroll
            for (int c = 0; c < 8; ++c) s_g[c * G5 + tid] = acc[c];
            __syncthreads();
            for (int idx = tid; idx < 8 * D; idx += NTH) {
                int c = idx >> 6;
                int d = idx & 63;
                int cell = c0 + c;
                if (cell < n_out) {
                    const float* g = s_g + c * G5;
                    float cc = sigf(g[d]) * tanhf(g[2 * D + d])
                             + sigf(g[3 * D + d]) * c_src[(2 * cell) * D + d]
                             + sigf(g[4 * D + d]) * c_src[(2 * cell + 1) * D + d];
                    float hh = sigf(g[D + d]) * tanhf(cc);
                    c_dst[cell * D + d] = cc;
                    h_dst[cell * D + d] = hh;
                }
            }
            __syncthreads();
        }
        n = n_out; src = dst; ++level;
    }

    // Summary fold over per-level representatives; root in buffer 'src'.
    {
        const float* rh = (src == 1) ? g_A_h : g_B_h;
        const float* rc = (src == 1) ? g_A_c : g_B_c;
        if (tid < D) { sh[tid] = rh[tid]; sc2[tid] = rc[tid]; }
        __syncthreads();

        for (int l = n_lvls_total - 1; l >= 0; --l) {
            const float* lh = g_lvl_h + l * D;
            float acc = sb[tid];
#pragma unroll 8
            for (int k = 0; k < D; ++k) {
                acc = fmaf(sh[k], sWl[k * G5 + tid], acc);
                acc = fmaf(lh[k], sWr[k * G5 + tid], acc);
            }
            s_g[tid] = acc;
            __syncthreads();
            if (tid < D) {
                const float* lc = g_lvl_c + l * D;
                float cc = sigf(s_g[tid]) * tanhf(s_g[2 * D + tid])
                         + sigf(s_g[3 * D + tid]) * sc2[tid]
                         + sigf(s_g[4 * D + tid]) * lc[tid];
                float hh = sigf(s_g[D + tid]) * tanhf(cc);
                sc2[tid] = cc;
                sh[tid] = hh;
            }
            __syncthreads();
        }
        if (tid < D) {
            out[tid]     = sh[tid];
            out[D + tid] = sc2[tid];
        }
    }
}

extern "C" void kernel_launch(void* const* d_in, const int* in_sizes, int n_in,
                              void* d_out, int out_size)
{
    const float* h_bot = (const float*)d_in[0];
    const float* c_bot = (const float*)d_in[1];
    const float* mWl   = (const float*)d_in[2];
    const float* mWr   = (const float*)d_in[3];
    const float* mb    = (const float*)d_in[4];
    const float* sWl   = (const float*)d_in[5];
    const float* sWr   = (const float*)d_in[6];
    const float* sb    = (const float*)d_in[7];

    int n = in_sizes[0] / D;   // 524288 leaves
    int level = 0;
    int src_sel = 0;
    while (n > 64) {
        int n_out = n >> 1;
        int dst_sel = (level & 1) ? 2 : 1;
        int blocks = (n_out + CPB - 1) / CPB;
        merge_kernel<<<blocks, NTH>>>(h_bot, c_bot, src_sel, dst_sel,
                                      mWl, mWr, mb, n_out, level);
        src_sel = dst_sel;
        n = n_out;
        ++level;
    }
    // Total level count = levels done + log2(remaining n).
    int total = level;
    for (int m = n; m > 1; m >>= 1) ++total;
    tail_kernel<<<1, NTH>>>(mWl, mWr, mb, sWl, sWr, sb,
                            n, src_sel, level, total, (float*)d_out);
}

// round 12
// speedup vs baseline: 1.4695x; 1.0688x over previous
#include <cuda_runtime.h>
#include <cuda_bf16.h>
#include <math.h>
#include <stdint.h>

#define D    64
#define G5   320
#define MT   128            // cells per block (GEMM M)
#define MMN  256            // threads in mma merge kernel (8 warps)
#define NTH  320            // tail / scalar threads
#define CPB  32             // scalar fallback: cells per block

// dynamic smem layout for merge_mma (bytes)
#define SM_XHI  0
#define SM_XLO  32768
#define SM_WHI  65536
#define SM_WLO  147456
#define SMEM_MM 229376      // 224 KB

// Scratch ping-pong buffers (allocation-free: __device__ globals).
__device__ __align__(16) float g_A_h[(1 << 18) * D];
__device__ __align__(16) float g_A_c[(1 << 18) * D];
__device__ __align__(16) float g_B_h[(1 << 17) * D];
__device__ __align__(16) float g_B_c[(1 << 17) * D];
// Per-level Fenwick representatives (last row of each level's INPUT), 19 levels.
__device__ float g_lvl_h[19 * D];
__device__ float g_lvl_c[19 * D];
// W^T = [Wl;Wr]^T as bf16 hi/lo, rows n=0..319, k=0..127, XOR-swizzled rows of
// 256B: byte = n*256 + ((k/8 ^ (n&7))*16) + (k&7)*2. Layout identical to SMEM.
__device__ __align__(16) __nv_bfloat16 g_WThi[320 * 128];
__device__ __align__(16) __nv_bfloat16 g_WTlo[320 * 128];

__device__ __forceinline__ float sigf(float x) {
    return 1.0f / (1.0f + expf(-x));
}
__device__ __forceinline__ void lstm1(float gi, float go, float gu, float gfl,
                                      float gfr, float cl, float cr,
                                      float& hh, float& cc) {
    cc = sigf(gi) * tanhf(gu) + sigf(gfl) * cl + sigf(gfr) * cr;
    hh = sigf(go) * tanhf(cc);
}
__device__ __forceinline__ uint32_t smem_u32(const void* p) {
    uint32_t a;
    asm("{ .reg .u64 t; cvta.to.shared.u64 t, %1; cvt.u32.u64 %0, t; }"
        : "=r"(a) : "l"(p));
    return a;
}
__device__ __forceinline__ uint32_t bf2hi(float x, float y) {
    __nv_bfloat16 hx = __float2bfloat16(x), hy = __float2bfloat16(y);
    return (uint32_t)__bfloat16_as_ushort(hx)
         | ((uint32_t)__bfloat16_as_ushort(hy) << 16);
}
__device__ __forceinline__ void ldsm4(uint32_t& r0, uint32_t& r1, uint32_t& r2,
                                      uint32_t& r3, uint32_t addr) {
    asm volatile("ldmatrix.sync.aligned.m8n8.x4.shared.b16 {%0,%1,%2,%3}, [%4];"
                 : "=r"(r0), "=r"(r1), "=r"(r2), "=r"(r3) : "r"(addr));
}
__device__ __forceinline__ void ldsm2(uint32_t& r0, uint32_t& r1, uint32_t addr) {
    asm volatile("ldmatrix.sync.aligned.m8n8.x2.shared.b16 {%0,%1}, [%2];"
                 : "=r"(r0), "=r"(r1) : "r"(addr));
}
__device__ __forceinline__ void mma16816(float* c, const uint32_t* a,
                                         const uint32_t* b) {
    asm volatile("mma.sync.aligned.m16n8k16.row.col.f32.bf16.bf16.f32 "
                 "{%0,%1,%2,%3}, {%4,%5,%6,%7}, {%8,%9}, {%0,%1,%2,%3};"
                 : "+f"(c[0]), "+f"(c[1]), "+f"(c[2]), "+f"(c[3])
                 : "r"(a[0]), "r"(a[1]), "r"(a[2]), "r"(a[3]),
                   "r"(b[0]), "r"(b[1]));
}

// ---- One-time weight prep: W^T, bf16 split, swizzled (matches smem) ----
__global__ void prep_w(const float* __restrict__ Wl, const float* __restrict__ Wr)
{
    int idx = blockIdx.x * blockDim.x + threadIdx.x;
    if (idx < 320 * 128) {
        int k = idx & 127;
        int n = idx >> 7;
        float w = (k < 64) ? Wl[k * G5 + n] : Wr[(k - 64) * G5 + n];
        __nv_bfloat16 hi = __float2bfloat16(w);
        __nv_bfloat16 lo = __float2bfloat16(w - __bfloat162float(hi));
        int byte = n * 256 + (((k >> 3) ^ (n & 7)) * 16) + (k & 7) * 2;
        g_WThi[byte >> 1] = hi;
        g_WTlo[byte >> 1] = lo;
    }
}

// ---- HMMA merge level: block = 128 cells, full 320 gate columns ----
__global__ __launch_bounds__(MMN, 1)
void merge_mma(const float* __restrict__ hb, const float* __restrict__ cb,
               int src_sel, int dst_sel,
               const float* __restrict__ bias, int n_out, int level)
{
    const float* h_src = (src_sel == 0) ? hb : (src_sel == 1 ? g_A_h : g_B_h);
    const float* c_src = (src_sel == 0) ? cb : (src_sel == 1 ? g_A_c : g_B_c);
    float* h_dst = (dst_sel == 1) ? g_A_h : g_B_h;
    float* c_dst = (dst_sel == 1) ? g_A_c : g_B_c;

    extern __shared__ __align__(1024) char sm[];
    const uint32_t smu = smem_u32(sm);
    const int tid = threadIdx.x;
    const int cell0 = blockIdx.x * MT;

    if (blockIdx.x == 0 && tid < D) {
        int last = 2 * n_out - 1;
        g_lvl_h[level * D + tid] = h_src[(size_t)last * D + tid];
        g_lvl_c[level * D + tid] = c_src[(size_t)last * D + tid];
    }

    // ---- Stage X (bf16 hi/lo, swizzled 256B rows) ----
    {
        int row  = tid & 127;              // cell row 0..127
        int half = tid >> 7;               // k half: 0 -> hl, 1 -> hr
        int cell = cell0 + row;
        bool valid = cell < n_out;
        const float4* src4 =
            reinterpret_cast<const float4*>(h_src + ((size_t)(2 * cell) + half) * D);
        char* bh = sm + SM_XHI + row * 256;
        char* bl = sm + SM_XLO + row * 256;
#pragma unroll
        for (int jc = 0; jc < 8; ++jc) {
            float4 a = make_float4(0.f, 0.f, 0.f, 0.f), b = a;
            if (valid) { a = src4[2 * jc]; b = src4[2 * jc + 1]; }
            uint4 hv, lv;
            hv.x = bf2hi(a.x, a.y); hv.y = bf2hi(a.z, a.w);
            hv.z = bf2hi(b.x, b.y); hv.w = bf2hi(b.z, b.w);
            float r0 = a.x - __bfloat162float(__float2bfloat16(a.x));
            float r1 = a.y - __bfloat162float(__float2bfloat16(a.y));
            float r2 = a.z - __bfloat162float(__float2bfloat16(a.z));
            float r3 = a.w - __bfloat162float(__float2bfloat16(a.w));
            float r4 = b.x - __bfloat162float(__float2bfloat16(b.x));
            float r5 = b.y - __bfloat162float(__float2bfloat16(b.y));
            float r6 = b.z - __bfloat162float(__float2bfloat16(b.z));
            float r7 = b.w - __bfloat162float(__float2bfloat16(b.w));
            lv.x = bf2hi(r0, r1); lv.y = bf2hi(r2, r3);
            lv.z = bf2hi(r4, r5); lv.w = bf2hi(r6, r7);
            int c16 = half * 8 + jc;
            int loc = ((c16 ^ (row & 7)) * 16);
            *reinterpret_cast<uint4*>(bh + loc) = hv;
            *reinterpret_cast<uint4*>(bl + loc) = lv;
        }
    }

    // ---- Copy pre-swizzled W^T (hi+lo) into smem ----
    {
        const uint4* wh = reinterpret_cast<const uint4*>(g_WThi);
        const uint4* wl = reinterpret_cast<const uint4*>(g_WTlo);
        uint4* dh = reinterpret_cast<uint4*>(sm + SM_WHI);
        uint4* dl = reinterpret_cast<uint4*>(sm + SM_WLO);
        for (int i = tid; i < 5120; i += MMN) {
            dh[i] = wh[i];
            dl[i] = wl[i];
        }
    }
    __syncthreads();

    // ---- Warp GEMM + in-register LSTM epilogue ----
    {
        const int w    = tid >> 5;
        const int lane = tid & 31;
        const int gr   = lane >> 2;
        const int gc   = lane & 3;
        const int ct   = w;
        const int arl  = lane & 15;
        const int asel = lane >> 4;
        const int brl  = lane & 7;
        const int bsel = (lane >> 3) & 1;

        for (int rt = 0; rt < 8; ++rt) {
            float acc[5][4];
#pragma unroll
            for (int g = 0; g < 5; ++g)
#pragma unroll
                for (int q = 0; q < 4; ++q) acc[g][q] = 0.0f;

            const uint32_t abase = (rt * 16 + arl) * 256;
#pragma unroll
            for (int ks = 0; ks < 8; ++ks) {
                uint32_t aswz = abase + (((2 * ks + asel) ^ (arl & 7)) * 16);
                uint32_t ah[4], al[4];
                ldsm4(ah[0], ah[1], ah[2], ah[3], smu + SM_XHI + aswz);
                ldsm4(al[0], al[1], al[2], al[3], smu + SM_XLO + aswz);
#pragma unroll
                for (int g = 0; g < 5; ++g) {
                    uint32_t brow = g * 64 + ct * 8 + brl;
                    uint32_t bswz = brow * 256 + (((2 * ks + bsel) ^ brl) * 16);
                    uint32_t bh[2], bl[2];
                    ldsm2(bh[0], bh[1], smu + SM_WHI + bswz);
                    ldsm2(bl[0], bl[1], smu + SM_WLO + bswz);
                    mma16816(acc[g], ah, bh);   // hi * hi
                    mma16816(acc[g], al, bh);   // lo * hi
                    mma16816(acc[g], ah, bl);   // hi * lo
                }
            }

            const int d0 = ct * 8 + gc * 2;
#pragma unroll
            for (int half = 0; half < 2; ++half) {
                int cell = cell0 + rt * 16 + gr + half * 8;
                if (cell < n_out) {
                    int q = half * 2;
                    float2 cl = *reinterpret_cast<const float2*>(
                        c_src + (size_t)(2 * cell) * D + d0);
                    float2 cr = *reinterpret_cast<const float2*>(
                        c_src + (size_t)(2 * cell + 1) * D + d0);
                    float2 bi  = *reinterpret_cast<const float2*>(bias + 0 * D + d0);
                    float2 bo  = *reinterpret_cast<const float2*>(bias + 1 * D + d0);
                    float2 bu  = *reinterpret_cast<const float2*>(bias + 2 * D + d0);
                    float2 bfl = *reinterpret_cast<const float2*>(bias + 3 * D + d0);
                    float2 bfr = *reinterpret_cast<const float2*>(bias + 4 * D + d0);
                    float h0, c0, h1, c1;
                    lstm1(acc[0][q] + bi.x, acc[1][q] + bo.x, acc[2][q] + bu.x,
                          acc[3][q] + bfl.x, acc[4][q] + bfr.x, cl.x, cr.x, h0, c0);
                    lstm1(acc[0][q+1] + bi.y, acc[1][q+1] + bo.y, acc[2][q+1] + bu.y,
                          acc[3][q+1] + bfl.y, acc[4][q+1] + bfr.y, cl.y, cr.y, h1, c1);
                    *reinterpret_cast<float2*>(h_dst + (size_t)cell * D + d0) =
                        make_float2(h0, h1);
                    *reinterpret_cast<float2*>(c_dst + (size_t)cell * D + d0) =
                        make_float2(c0, c1);
                }
            }
        }
    }
}

// ---- Scalar fallback merge (proven R2/R7 design), used if opt-in smem fails --
__global__ __launch_bounds__(NTH, 3)
void merge_scalar(const float* __restrict__ hb, const float* __restrict__ cb,
                  int src_sel, int dst_sel,
                  const float* __restrict__ Wl, const float* __restrict__ Wr,
                  const float* __restrict__ b,
                  int n_out, int level)
{
    const float* h_src = (src_sel == 0) ? hb : (src_sel == 1 ? g_A_h : g_B_h);
    const float* c_src = (src_sel == 0) ? cb : (src_sel == 1 ? g_A_c : g_B_c);
    float* h_dst = (dst_sel == 1) ? g_A_h : g_B_h;
    float* c_dst = (dst_sel == 1) ? g_A_c : g_B_c;

    __shared__ __align__(16) float s_buf[CPB * G5];

    const int tid   = threadIdx.x;
    const int cell0 = blockIdx.x * CPB;
    const int ct    = tid % 80;
    const int cg    = tid / 80;

    float* s_h2 = s_buf;
    {
        const float4* src4 = reinterpret_cast<const float4*>(h_src) + (size_t)cell0 * 32;
        for (int idx = tid; idx < CPB * 2 * 16; idx += NTH) {
            int r  = idx >> 4;
            int f4 = idx & 15;
            int c  = r >> 1;
            int lr = r & 1;
            float4 v = make_float4(0.f, 0.f, 0.f, 0.f);
            if (cell0 + c < n_out) v = src4[idx];
            float* dst = s_h2 + c * 128 + 8 * f4 + lr;
            dst[0] = v.x; dst[2] = v.y; dst[4] = v.z; dst[6] = v.w;
        }
    }
    __syncthreads();

    const float4* wl4 = reinterpret_cast<const float4*>(Wl);
    const float4* wr4 = reinterpret_cast<const float4*>(Wr);
    float4 b4 = reinterpret_cast<const float4*>(b)[ct];

    float acc[8][4];
#pragma unroll
    for (int c = 0; c < 8; ++c) {
        acc[c][0] = b4.x; acc[c][1] = b4.y; acc[c][2] = b4.z; acc[c][3] = b4.w;
    }
    const float4* hbase = reinterpret_cast<const float4*>(s_h2) + (cg * 8) * 32;

#pragma unroll 2
    for (int k2 = 0; k2 < 32; ++k2) {
        float4 wl0 = wl4[(2 * k2    ) * 80 + ct];
        float4 wr0 = wr4[(2 * k2    ) * 80 + ct];
        float4 wl1 = wl4[(2 * k2 + 1) * 80 + ct];
        float4 wr1 = wr4[(2 * k2 + 1) * 80 + ct];
#pragma unroll
        for (int c = 0; c < 8; ++c) {
            float4 hv = hbase[c * 32 + k2];
            float a0 = acc[c][0], a1 = acc[c][1], a2 = acc[c][2], a3 = acc[c][3];
            a0 = fmaf(wl0.x, hv.x, a0); a1 = fmaf(wl0.y, hv.x, a1);
            a2 = fmaf(wl0.z, hv.x, a2); a3 = fmaf(wl0.w, hv.x, a3);
            a0 = fmaf(wr0.x, hv.y, a0); a1 = fmaf(wr0.y, hv.y, a1);
            a2 = fmaf(wr0.z, hv.y, a2); a3 = fmaf(wr0.w, hv.y, a3);
            a0 = fmaf(wl1.x, hv.z, a0); a1 = fmaf(wl1.y, hv.z, a1);
            a2 = fmaf(wl1.z, hv.z, a2); a3 = fmaf(wl1.w, hv.z, a3);
            a0 = fmaf(wr1.x, hv.w, a0); a1 = fmaf(wr1.y, hv.w, a1);
            a2 = fmaf(wr1.z, hv.w, a2); a3 = fmaf(wr1.w, hv.w, a3);
            acc[c][0] = a0; acc[c][1] = a1; acc[c][2] = a2; acc[c][3] = a3;
        }
    }
    __syncthreads();
#pragma unroll
    for (int c = 0; c < 8; ++c) {
        float4* p = reinterpret_cast<float4*>(s_buf + (cg * 8 + c) * G5) + ct;
        *p = make_float4(acc[c][0], acc[c][1], acc[c][2], acc[c][3]);
    }
    __syncthreads();

    for (int idx = tid; idx < CPB * D; idx += NTH) {
        int c = idx >> 6;
        int d = idx & 63;
        int cell = cell0 + c;
        if (cell < n_out) {
            const float* g = s_buf + c * G5;
            float cc, hh;
            lstm1(g[d], g[D + d], g[2 * D + d], g[3 * D + d], g[4 * D + d],
                  c_src[(size_t)(2 * cell) * D + d],
                  c_src[(size_t)(2 * cell + 1) * D + d], hh, cc);
            c_dst[(size_t)cell * D + d] = cc;
            h_dst[(size_t)cell * D + d] = hh;
        }
    }

    if (blockIdx.x == 0 && tid < D) {
        int last = 2 * n_out - 1;
        g_lvl_h[level * D + tid] = h_src[(size_t)last * D + tid];
        g_lvl_c[level * D + tid] = c_src[(size_t)last * D + tid];
    }
}

// ---- Single-block tail (n <= 64) + summary fold ----
__global__ __launch_bounds__(NTH)
void tail_kernel(const float* __restrict__ mWl, const float* __restrict__ mWr,
                 const float* __restrict__ mb,
                 const float* __restrict__ sWl, const float* __restrict__ sWr,
                 const float* __restrict__ sb,
                 int n_start, int src_sel, int level_start, int n_lvls_total,
                 float* __restrict__ out)
{
    __shared__ float s_h[64 * D];
    __shared__ float s_g[8 * G5];
    __shared__ float sh[D], sc2[D];

    const int tid = threadIdx.x;
    int n = n_start, src = src_sel, level = level_start;

    while (n > 1) {
        const float* h_src = (src == 1) ? g_A_h : g_B_h;
        const float* c_src = (src == 1) ? g_A_c : g_B_c;
        int dst = (level & 1) ? 2 : 1;
        float* h_dst = (dst == 1) ? g_A_h : g_B_h;
        float* c_dst = (dst == 1) ? g_A_c : g_B_c;

        if (tid < D) {
            g_lvl_h[level * D + tid] = h_src[(n - 1) * D + tid];
            g_lvl_c[level * D + tid] = c_src[(n - 1) * D + tid];
        }
        for (int i = tid; i < n * D; i += NTH) s_h[i] = h_src[i];
        __syncthreads();

        int n_out = n >> 1;
        for (int c0 = 0; c0 < n_out; c0 += 8) {
            float acc[8];
            float bv = mb[tid];
#pragma unroll
            for (int c = 0; c < 8; ++c) acc[c] = bv;
            for (int k = 0; k < D; ++k) {
                float wlv = mWl[k * G5 + tid];
                float wrv = mWr[k * G5 + tid];
#pragma unroll
                for (int c = 0; c < 8; ++c) {
                    int cell = c0 + c;
                    if (cell < n_out) {
                        acc[c] = fmaf(s_h[(2 * cell) * D + k], wlv, acc[c]);
                        acc[c] = fmaf(s_h[(2 * cell + 1) * D + k], wrv, acc[c]);
                    }
                }
            }
#pragma unroll
            for (int c = 0; c < 8; ++c) s_g[c * G5 + tid] = acc[c];
            __syncthreads();
            for (int idx = tid; idx < 8 * D; idx += NTH) {
                int c = idx >> 6;
                int d = idx & 63;
                int cell = c0 + c;
                if (cell < n_out) {
                    const float* g = s_g + c * G5;
                    float cc = sigf(g[d]) * tanhf(g[2 * D + d])
                             + sigf(g[3 * D + d]) * c_src[(2 * cell) * D + d]
                             + sigf(g[4 * D + d]) * c_src[(2 * cell + 1) * D + d];
                    float hh = sigf(g[D + d]) * tanhf(cc);
                    c_dst[cell * D + d] = cc;
                    h_dst[cell * D + d] = hh;
                }
            }
            __syncthreads();
        }
        n = n_out; src = dst; ++level;
    }

    {
        const float* rh = (src == 1) ? g_A_h : g_B_h;
        const float* rc = (src == 1) ? g_A_c : g_B_c;
        if (tid < D) { sh[tid] = rh[tid]; sc2[tid] = rc[tid]; }
        __syncthreads();

        for (int l = n_lvls_total - 1; l >= 0; --l) {
            const float* lh = g_lvl_h + l * D;
            float acc = sb[tid];
#pragma unroll 8
            for (int k = 0; k < D; ++k) {
                acc = fmaf(sh[k], sWl[k * G5 + tid], acc);
                acc = fmaf(lh[k], sWr[k * G5 + tid], acc);
            }
            s_g[tid] = acc;
            __syncthreads();
            if (tid < D) {
                const float* lc = g_lvl_c + l * D;
                float cc = sigf(s_g[tid]) * tanhf(s_g[2 * D + tid])
                         + sigf(s_g[3 * D + tid]) * sc2[tid]
                         + sigf(s_g[4 * D + tid]) * lc[tid];
                float hh = sigf(s_g[D + tid]) * tanhf(cc);
                sc2[tid] = cc;
                sh[tid] = hh;
            }
            __syncthreads();
        }
        if (tid < D) {
            out[tid]     = sh[tid];
            out[D + tid] = sc2[tid];
        }
    }
}

extern "C" void kernel_launch(void* const* d_in, const int* in_sizes, int n_in,
                              void* d_out, int out_size)
{
    const float* h_bot = (const float*)d_in[0];
    const float* c_bot = (const float*)d_in[1];
    const float* mWl   = (const float*)d_in[2];
    const float* mWr   = (const float*)d_in[3];
    const float* mb    = (const float*)d_in[4];
    const float* sWl   = (const float*)d_in[5];
    const float* sWr   = (const float*)d_in[6];
    const float* sb    = (const float*)d_in[7];

    cudaError_t attr_ok =
        cudaFuncSetAttribute(merge_mma, cudaFuncAttributeMaxDynamicSharedMemorySize,
                             SMEM_MM);
    bool use_mma = (attr_ok == cudaSuccess);

    if (use_mma) prep_w<<<(320 * 128 + 255) / 256, 256>>>(mWl, mWr);

    int n = in_sizes[0] / D;   // 524288
    int level = 0;
    int src_sel = 0;
    while (n >= 128) {
        int n_out = n >> 1;
        int dst_sel = (level & 1) ? 2 : 1;
        if (use_mma) {
            merge_mma<<<(n_out + MT - 1) / MT, MMN, SMEM_MM>>>(
                h_bot, c_bot, src_sel, dst_sel, mb, n_out, level);
        } else {
            merge_scalar<<<(n_out + CPB - 1) / CPB, NTH>>>(
                h_bot, c_bot, src_sel, dst_sel, mWl, mWr, mb, n_out, level);
        }
        src_sel = dst_sel;
        n = n_out;
        ++level;
    }
    int total = level;
    for (int m = n; m > 1; m >>= 1) ++total;
    tail_kernel<<<1, NTH>>>(mWl, mWr, mb, sWl, sWr, sb,
                            n, src_sel, level, total, (float*)d_out);
}

// round 13
// speedup vs baseline: 1.8292x; 1.2448x over previous
#include <cuda_runtime.h>
#include <cuda_bf16.h>
#include <math.h>
#include <stdint.h>

#define D    64
#define G5   320
#define MT   128            // cells per block (GEMM M)
#define MMN  512            // threads in mma merge kernel (16 warps)
#define NTH  320            // tail / scalar threads
#define CPB  32             // scalar fallback: cells per block

// dynamic smem layout for merge_mma (bytes)
#define SM_XHI  0
#define SM_XLO  32768
#define SM_WHI  65536
#define SM_WLO  147456
#define SMEM_MM 229376      // 224 KB

// Scratch ping-pong buffers (allocation-free: __device__ globals).
__device__ __align__(16) float g_A_h[(1 << 18) * D];
__device__ __align__(16) float g_A_c[(1 << 18) * D];
__device__ __align__(16) float g_B_h[(1 << 17) * D];
__device__ __align__(16) float g_B_c[(1 << 17) * D];
// Per-level Fenwick representatives (last row of each level's INPUT), 19 levels.
__device__ float g_lvl_h[19 * D];
__device__ float g_lvl_c[19 * D];
// W^T = [Wl;Wr]^T as bf16 hi/lo, rows n=0..319, k=0..127, XOR-swizzled rows of
// 256B: byte = n*256 + ((k/8 ^ (n&7))*16) + (k&7)*2. Layout identical to SMEM.
__device__ __align__(16) __nv_bfloat16 g_WThi[320 * 128];
__device__ __align__(16) __nv_bfloat16 g_WTlo[320 * 128];

__device__ __forceinline__ float sigf(float x) {
    return 1.0f / (1.0f + expf(-x));
}
__device__ __forceinline__ void lstm1(float gi, float go, float gu, float gfl,
                                      float gfr, float cl, float cr,
                                      float& hh, float& cc) {
    cc = sigf(gi) * tanhf(gu) + sigf(gfl) * cl + sigf(gfr) * cr;
    hh = sigf(go) * tanhf(cc);
}
__device__ __forceinline__ uint32_t smem_u32(const void* p) {
    uint32_t a;
    asm("{ .reg .u64 t; cvta.to.shared.u64 t, %1; cvt.u32.u64 %0, t; }"
        : "=r"(a) : "l"(p));
    return a;
}
__device__ __forceinline__ uint32_t bf2hi(float x, float y) {
    __nv_bfloat16 hx = __float2bfloat16(x), hy = __float2bfloat16(y);
    return (uint32_t)__bfloat16_as_ushort(hx)
         | ((uint32_t)__bfloat16_as_ushort(hy) << 16);
}
__device__ __forceinline__ void ldsm4(uint32_t& r0, uint32_t& r1, uint32_t& r2,
                                      uint32_t& r3, uint32_t addr) {
    asm volatile("ldmatrix.sync.aligned.m8n8.x4.shared.b16 {%0,%1,%2,%3}, [%4];"
                 : "=r"(r0), "=r"(r1), "=r"(r2), "=r"(r3) : "r"(addr));
}
__device__ __forceinline__ void ldsm2(uint32_t& r0, uint32_t& r1, uint32_t addr) {
    asm volatile("ldmatrix.sync.aligned.m8n8.x2.shared.b16 {%0,%1}, [%2];"
                 : "=r"(r0), "=r"(r1) : "r"(addr));
}
__device__ __forceinline__ void mma16816(float* c, const uint32_t* a,
                                         const uint32_t* b) {
    asm volatile("mma.sync.aligned.m16n8k16.row.col.f32.bf16.bf16.f32 "
                 "{%0,%1,%2,%3}, {%4,%5,%6,%7}, {%8,%9}, {%0,%1,%2,%3};"
                 : "+f"(c[0]), "+f"(c[1]), "+f"(c[2]), "+f"(c[3])
                 : "r"(a[0]), "r"(a[1]), "r"(a[2]), "r"(a[3]),
                   "r"(b[0]), "r"(b[1]));
}

// ---- One-time weight prep: W^T, bf16 split, swizzled (matches smem) ----
__global__ void prep_w(const float* __restrict__ Wl, const float* __restrict__ Wr)
{
    int idx = blockIdx.x * blockDim.x + threadIdx.x;
    if (idx < 320 * 128) {
        int k = idx & 127;
        int n = idx >> 7;
        float w = (k < 64) ? Wl[k * G5 + n] : Wr[(k - 64) * G5 + n];
        __nv_bfloat16 hi = __float2bfloat16(w);
        __nv_bfloat16 lo = __float2bfloat16(w - __bfloat162float(hi));
        int byte = n * 256 + (((k >> 3) ^ (n & 7)) * 16) + (k & 7) * 2;
        g_WThi[byte >> 1] = hi;
        g_WTlo[byte >> 1] = lo;
    }
}

// ---- HMMA merge level: block = 128 cells, full 320 gate columns, 16 warps ----
__global__ __launch_bounds__(MMN, 1)
void merge_mma(const float* __restrict__ hb, const float* __restrict__ cb,
               int src_sel, int dst_sel,
               const float* __restrict__ bias, int n_out, int level)
{
    const float* h_src = (src_sel == 0) ? hb : (src_sel == 1 ? g_A_h : g_B_h);
    const float* c_src = (src_sel == 0) ? cb : (src_sel == 1 ? g_A_c : g_B_c);
    float* h_dst = (dst_sel == 1) ? g_A_h : g_B_h;
    float* c_dst = (dst_sel == 1) ? g_A_c : g_B_c;

    extern __shared__ __align__(1024) char sm[];
    const uint32_t smu = smem_u32(sm);
    const int tid = threadIdx.x;
    const int cell0 = blockIdx.x * MT;

    if (blockIdx.x == 0 && tid < D) {
        int last = 2 * n_out - 1;
        g_lvl_h[level * D + tid] = h_src[(size_t)last * D + tid];
        g_lvl_c[level * D + tid] = c_src[(size_t)last * D + tid];
    }

    // ---- Stage X (bf16 hi/lo, swizzled 256B rows). 512 thr: 4 jc each ----
    {
        int row  = tid & 127;              // cell row 0..127
        int part = tid >> 7;               // 0..3
        int half = part >> 1;              // k half: 0 -> hl, 1 -> hr
        int sub  = part & 1;               // jc quartet select
        int cell = cell0 + row;
        bool valid = cell < n_out;
        const float4* src4 =
            reinterpret_cast<const float4*>(h_src + ((size_t)(2 * cell) + half) * D);
        char* bh = sm + SM_XHI + row * 256;
        char* bl = sm + SM_XLO + row * 256;
#pragma unroll
        for (int j = 0; j < 4; ++j) {
            int jc = sub * 4 + j;
            float4 a = make_float4(0.f, 0.f, 0.f, 0.f), b = a;
            if (valid) { a = src4[2 * jc]; b = src4[2 * jc + 1]; }
            uint4 hv, lv;
            hv.x = bf2hi(a.x, a.y); hv.y = bf2hi(a.z, a.w);
            hv.z = bf2hi(b.x, b.y); hv.w = bf2hi(b.z, b.w);
            float r0 = a.x - __bfloat162float(__float2bfloat16(a.x));
            float r1 = a.y - __bfloat162float(__float2bfloat16(a.y));
            float r2 = a.z - __bfloat162float(__float2bfloat16(a.z));
            float r3 = a.w - __bfloat162float(__float2bfloat16(a.w));
            float r4 = b.x - __bfloat162float(__float2bfloat16(b.x));
            float r5 = b.y - __bfloat162float(__float2bfloat16(b.y));
            float r6 = b.z - __bfloat162float(__float2bfloat16(b.z));
            float r7 = b.w - __bfloat162float(__float2bfloat16(b.w));
            lv.x = bf2hi(r0, r1); lv.y = bf2hi(r2, r3);
            lv.z = bf2hi(r4, r5); lv.w = bf2hi(r6, r7);
            int c16 = half * 8 + jc;
            int loc = ((c16 ^ (row & 7)) * 16);
            *reinterpret_cast<uint4*>(bh + loc) = hv;
            *reinterpret_cast<uint4*>(bl + loc) = lv;
        }
    }

    // ---- Copy pre-swizzled W^T (hi+lo) into smem ----
    {
        const uint4* wh = reinterpret_cast<const uint4*>(g_WThi);
        const uint4* wl = reinterpret_cast<const uint4*>(g_WTlo);
        uint4* dh = reinterpret_cast<uint4*>(sm + SM_WHI);
        uint4* dl = reinterpret_cast<uint4*>(sm + SM_WLO);
        for (int i = tid; i < 5120; i += MMN) {
            dh[i] = wh[i];
            dl[i] = wl[i];
        }
    }
    __syncthreads();

    // ---- Warp GEMM + in-register LSTM epilogue ----
    {
        const int w    = tid >> 5;
        const int lane = tid & 31;
        const int gr   = lane >> 2;
        const int gc   = lane & 3;
        const int ct   = w & 7;            // n8 col tile within each 64 chunk
        const int rt0  = (w >> 3) * 4;     // rt half: warps 0-7 -> 0..3, 8-15 -> 4..7
        const int arl  = lane & 15;
        const int asel = lane >> 4;
        const int brl  = lane & 7;
        const int bsel = (lane >> 3) & 1;
        const int d0   = ct * 8 + gc * 2;

        // Bias for this thread's 2 d-columns, all 5 gates (constant over rt).
        float2 bi  = *reinterpret_cast<const float2*>(bias + 0 * D + d0);
        float2 bo  = *reinterpret_cast<const float2*>(bias + 1 * D + d0);
        float2 bu  = *reinterpret_cast<const float2*>(bias + 2 * D + d0);
        float2 bfl = *reinterpret_cast<const float2*>(bias + 3 * D + d0);
        float2 bfr = *reinterpret_cast<const float2*>(bias + 4 * D + d0);

        for (int rt = rt0; rt < rt0 + 4; ++rt) {
            float acc[5][4];
#pragma unroll
            for (int g = 0; g < 5; ++g)
#pragma unroll
                for (int q = 0; q < 4; ++q) acc[g][q] = 0.0f;

            const uint32_t abase = (rt * 16 + arl) * 256;
#pragma unroll
            for (int ks = 0; ks < 8; ++ks) {
                uint32_t aswz = abase + (((2 * ks + asel) ^ (arl & 7)) * 16);
                uint32_t ah[4], al[4];
                ldsm4(ah[0], ah[1], ah[2], ah[3], smu + SM_XHI + aswz);
                ldsm4(al[0], al[1], al[2], al[3], smu + SM_XLO + aswz);
#pragma unroll
                for (int g = 0; g < 5; ++g) {
                    uint32_t brow = g * 64 + ct * 8 + brl;
                    uint32_t bswz = brow * 256 + (((2 * ks + bsel) ^ brl) * 16);
                    uint32_t bh[2], bl[2];
                    ldsm2(bh[0], bh[1], smu + SM_WHI + bswz);
                    ldsm2(bl[0], bl[1], smu + SM_WLO + bswz);
                    mma16816(acc[g], ah, bh);   // hi * hi
                    mma16816(acc[g], al, bh);   // lo * hi
                    mma16816(acc[g], ah, bl);   // hi * lo
                }
            }

#pragma unroll
            for (int half = 0; half < 2; ++half) {
                int cell = cell0 + rt * 16 + gr + half * 8;
                if (cell < n_out) {
                    int q = half * 2;
                    float2 cl = *reinterpret_cast<const float2*>(
                        c_src + (size_t)(2 * cell) * D + d0);
                    float2 cr = *reinterpret_cast<const float2*>(
                        c_src + (size_t)(2 * cell + 1) * D + d0);
                    float h0, c0, h1, c1;
                    lstm1(acc[0][q] + bi.x, acc[1][q] + bo.x, acc[2][q] + bu.x,
                          acc[3][q] + bfl.x, acc[4][q] + bfr.x, cl.x, cr.x, h0, c0);
                    lstm1(acc[0][q+1] + bi.y, acc[1][q+1] + bo.y, acc[2][q+1] + bu.y,
                          acc[3][q+1] + bfl.y, acc[4][q+1] + bfr.y, cl.y, cr.y, h1, c1);
                    *reinterpret_cast<float2*>(h_dst + (size_t)cell * D + d0) =
                        make_float2(h0, h1);
                    *reinterpret_cast<float2*>(c_dst + (size_t)cell * D + d0) =
                        make_float2(c0, c1);
                }
            }
        }
    }
}

// ---- Scalar fallback merge (proven R2/R7 design), used if opt-in smem fails --
__global__ __launch_bounds__(NTH, 3)
void merge_scalar(const float* __restrict__ hb, const float* __restrict__ cb,
                  int src_sel, int dst_sel,
                  const float* __restrict__ Wl, const float* __restrict__ Wr,
                  const float* __restrict__ b,
                  int n_out, int level)
{
    const float* h_src = (src_sel == 0) ? hb : (src_sel == 1 ? g_A_h : g_B_h);
    const float* c_src = (src_sel == 0) ? cb : (src_sel == 1 ? g_A_c : g_B_c);
    float* h_dst = (dst_sel == 1) ? g_A_h : g_B_h;
    float* c_dst = (dst_sel == 1) ? g_A_c : g_B_c;

    __shared__ __align__(16) float s_buf[CPB * G5];

    const int tid   = threadIdx.x;
    const int cell0 = blockIdx.x * CPB;
    const int ct    = tid % 80;
    const int cg    = tid / 80;

    float* s_h2 = s_buf;
    {
        const float4* src4 = reinterpret_cast<const float4*>(h_src) + (size_t)cell0 * 32;
        for (int idx = tid; idx < CPB * 2 * 16; idx += NTH) {
            int r  = idx >> 4;
            int f4 = idx & 15;
            int c  = r >> 1;
            int lr = r & 1;
            float4 v = make_float4(0.f, 0.f, 0.f, 0.f);
            if (cell0 + c < n_out) v = src4[idx];
            float* dst = s_h2 + c * 128 + 8 * f4 + lr;
            dst[0] = v.x; dst[2] = v.y; dst[4] = v.z; dst[6] = v.w;
        }
    }
    __syncthreads();

    const float4* wl4 = reinterpret_cast<const float4*>(Wl);
    const float4* wr4 = reinterpret_cast<const float4*>(Wr);
    float4 b4 = reinterpret_cast<const float4*>(b)[ct];

    float acc[8][4];
#pragma unroll
    for (int c = 0; c < 8; ++c) {
        acc[c][0] = b4.x; acc[c][1] = b4.y; acc[c][2] = b4.z; acc[c][3] = b4.w;
    }
    const float4* hbase = reinterpret_cast<const float4*>(s_h2) + (cg * 8) * 32;

#pragma unroll 2
    for (int k2 = 0; k2 < 32; ++k2) {
        float4 wl0 = wl4[(2 * k2    ) * 80 + ct];
        float4 wr0 = wr4[(2 * k2    ) * 80 + ct];
        float4 wl1 = wl4[(2 * k2 + 1) * 80 + ct];
        float4 wr1 = wr4[(2 * k2 + 1) * 80 + ct];
#pragma unroll
        for (int c = 0; c < 8; ++c) {
            float4 hv = hbase[c * 32 + k2];
            float a0 = acc[c][0], a1 = acc[c][1], a2 = acc[c][2], a3 = acc[c][3];
            a0 = fmaf(wl0.x, hv.x, a0); a1 = fmaf(wl0.y, hv.x, a1);
            a2 = fmaf(wl0.z, hv.x, a2); a3 = fmaf(wl0.w, hv.x, a3);
            a0 = fmaf(wr0.x, hv.y, a0); a1 = fmaf(wr0.y, hv.y, a1);
            a2 = fmaf(wr0.z, hv.y, a2); a3 = fmaf(wr0.w, hv.y, a3);
            a0 = fmaf(wl1.x, hv.z, a0); a1 = fmaf(wl1.y, hv.z, a1);
            a2 = fmaf(wl1.z, hv.z, a2); a3 = fmaf(wl1.w, hv.z, a3);
            a0 = fmaf(wr1.x, hv.w, a0); a1 = fmaf(wr1.y, hv.w, a1);
            a2 = fmaf(wr1.z, hv.w, a2); a3 = fmaf(wr1.w, hv.w, a3);
            acc[c][0] = a0; acc[c][1] = a1; acc[c][2] = a2; acc[c][3] = a3;
        }
    }
    __syncthreads();
#pragma unroll
    for (int c = 0; c < 8; ++c) {
        float4* p = reinterpret_cast<float4*>(s_buf + (cg * 8 + c) * G5) + ct;
        *p = make_float4(acc[c][0], acc[c][1], acc[c][2], acc[c][3]);
    }
    __syncthreads();

    for (int idx = tid; idx < CPB * D; idx += NTH) {
        int c = idx >> 6;
        int d = idx & 63;
        int cell = cell0 + c;
        if (cell < n_out) {
            const float* g = s_buf + c * G5;
            float cc, hh;
            lstm1(g[d], g[D + d], g[2 * D + d], g[3 * D + d], g[4 * D + d],
                  c_src[(size_t)(2 * cell) * D + d],
                  c_src[(size_t)(2 * cell + 1) * D + d], hh, cc);
            c_dst[(size_t)cell * D + d] = cc;
            h_dst[(size_t)cell * D + d] = hh;
        }
    }

    if (blockIdx.x == 0 && tid < D) {
        int last = 2 * n_out - 1;
        g_lvl_h[level * D + tid] = h_src[(size_t)last * D + tid];
        g_lvl_c[level * D + tid] = c_src[(size_t)last * D + tid];
    }
}

// ---- Single-block tail (n <= 64) + summary fold ----
__global__ __launch_bounds__(NTH)
void tail_kernel(const float* __restrict__ mWl, const float* __restrict__ mWr,
                 const float* __restrict__ mb,
                 const float* __restrict__ sWl, const float* __restrict__ sWr,
                 const float* __restrict__ sb,
                 int n_start, int src_sel, int level_start, int n_lvls_total,
                 float* __restrict__ out)
{
    __shared__ float s_h[64 * D];
    __shared__ float s_g[8 * G5];
    __shared__ float sh[D], sc2[D];

    const int tid = threadIdx.x;
    int n = n_start, src = src_sel, level = level_start;

    while (n > 1) {
        const float* h_src = (src == 1) ? g_A_h : g_B_h;
        const float* c_src = (src == 1) ? g_A_c : g_B_c;
        int dst = (level & 1) ? 2 : 1;
        float* h_dst = (dst == 1) ? g_A_h : g_B_h;
        float* c_dst = (dst == 1) ? g_A_c : g_B_c;

        if (tid < D) {
            g_lvl_h[level * D + tid] = h_src[(n - 1) * D + tid];
            g_lvl_c[level * D + tid] = c_src[(n - 1) * D + tid];
        }
        for (int i = tid; i < n * D; i += NTH) s_h[i] = h_src[i];
        __syncthreads();

        int n_out = n >> 1;
        for (int c0 = 0; c0 < n_out; c0 += 8) {
            float acc[8];
            float bv = mb[tid];
#pragma unroll
            for (int c = 0; c < 8; ++c) acc[c] = bv;
            for (int k = 0; k < D; ++k) {
                float wlv = mWl[k * G5 + tid];
                float wrv = mWr[k * G5 + tid];
#pragma unroll
                for (int c = 0; c < 8; ++c) {
                    int cell = c0 + c;
                    if (cell < n_out) {
                        acc[c] = fmaf(s_h[(2 * cell) * D + k], wlv, acc[c]);
                        acc[c] = fmaf(s_h[(2 * cell + 1) * D + k], wrv, acc[c]);
                    }
                }
            }
#pragma unroll
            for (int c = 0; c < 8; ++c) s_g[c * G5 + tid] = acc[c];
            __syncthreads();
            for (int idx = tid; idx < 8 * D; idx += NTH) {
                int c = idx >> 6;
                int d = idx & 63;
                int cell = c0 + c;
                if (cell < n_out) {
                    const float* g = s_g + c * G5;
                    float cc = sigf(g[d]) * tanhf(g[2 * D + d])
                             + sigf(g[3 * D + d]) * c_src[(2 * cell) * D + d]
                             + sigf(g[4 * D + d]) * c_src[(2 * cell + 1) * D + d];
                    float hh = sigf(g[D + d]) * tanhf(cc);
                    c_dst[cell * D + d] = cc;
                    h_dst[cell * D + d] = hh;
                }
            }
            __syncthreads();
        }
        n = n_out; src = dst; ++level;
    }

    {
        const float* rh = (src == 1) ? g_A_h : g_B_h;
        const float* rc = (src == 1) ? g_A_c : g_B_c;
        if (tid < D) { sh[tid] = rh[tid]; sc2[tid] = rc[tid]; }
        __syncthreads();

        for (int l = n_lvls_total - 1; l >= 0; --l) {
            const float* lh = g_lvl_h + l * D;
            float acc = sb[tid];
#pragma unroll 8
            for (int k = 0; k < D; ++k) {
                acc = fmaf(sh[k], sWl[k * G5 + tid], acc);
                acc = fmaf(lh[k], sWr[k * G5 + tid], acc);
            }
            s_g[tid] = acc;
            __syncthreads();
            if (tid < D) {
                const float* lc = g_lvl_c + l * D;
                float cc = sigf(s_g[tid]) * tanhf(s_g[2 * D + tid])
                         + sigf(s_g[3 * D + tid]) * sc2[tid]
                         + sigf(s_g[4 * D + tid]) * lc[tid];
                float hh = sigf(s_g[D + tid]) * tanhf(cc);
                sc2[tid] = cc;
                sh[tid] = hh;
            }
            __syncthreads();
        }
        if (tid < D) {
            out[tid]     = sh[tid];
            out[D + tid] = sc2[tid];
        }
    }
}

extern "C" void kernel_launch(void* const* d_in, const int* in_sizes, int n_in,
                              void* d_out, int out_size)
{
    const float* h_bot = (const float*)d_in[0];
    const float* c_bot = (const float*)d_in[1];
    const float* mWl   = (const float*)d_in[2];
    const float* mWr   = (const float*)d_in[3];
    const float* mb    = (const float*)d_in[4];
    const float* sWl   = (const float*)d_in[5];
    const float* sWr   = (const float*)d_in[6];
    const float* sb    = (const float*)d_in[7];

    cudaError_t attr_ok =
        cudaFuncSetAttribute(merge_mma, cudaFuncAttributeMaxDynamicSharedMemorySize,
                             SMEM_MM);
    bool use_mma = (attr_ok == cudaSuccess);

    if (use_mma) prep_w<<<(320 * 128 + 255) / 256, 256>>>(mWl, mWr);

    int n = in_sizes[0] / D;   // 524288
    int level = 0;
    int src_sel = 0;
    while (n >= 128) {
        int n_out = n >> 1;
        int dst_sel = (level & 1) ? 2 : 1;
        if (use_mma) {
            merge_mma<<<(n_out + MT - 1) / MT, MMN, SMEM_MM>>>(
                h_bot, c_bot, src_sel, dst_sel, mb, n_out, level);
        } else {
            merge_scalar<<<(n_out + CPB - 1) / CPB, NTH>>>(
                h_bot, c_bot, src_sel, dst_sel, mWl, mWr, mb, n_out, level);
        }
        src_sel = dst_sel;
        n = n_out;
        ++level;
    }
    int total = level;
    for (int m = n; m > 1; m >>= 1) ++total;
    tail_kernel<<<1, NTH>>>(mWl, mWr, mb, sWl, sWr, sb,
                            n, src_sel, level, total, (float*)d_out);
}

// round 15
// speedup vs baseline: 1.8755x; 1.0253x over previous
#include <cuda_runtime.h>
#include <cuda_bf16.h>
#include <math.h>
#include <stdint.h>

#define D    64
#define G5   320
#define MT   128            // cells per tile (GEMM M)
#define MMN  512            // threads in mma merge kernel (16 warps)
#define NTH  320            // tail / scalar threads
#define CPB  32             // scalar fallback: cells per block

// dynamic smem layout for merge_mma (bytes)
#define SM_XHI  0
#define SM_XLO  32768
#define SM_WHI  65536
#define SM_WLO  147456
#define SMEM_MM 229376      // 224 KB

// Scratch ping-pong buffers (allocation-free: __device__ globals).
__device__ __align__(16) float g_A_h[(1 << 18) * D];
__device__ __align__(16) float g_A_c[(1 << 18) * D];
__device__ __align__(16) float g_B_h[(1 << 17) * D];
__device__ __align__(16) float g_B_c[(1 << 17) * D];
// Per-level Fenwick representatives (last row of each level's INPUT), 19 levels.
__device__ float g_lvl_h[19 * D];
__device__ float g_lvl_c[19 * D];
// W^T = [Wl;Wr]^T as bf16 hi/lo, rows n=0..319, k=0..127, XOR-swizzled rows of
// 256B: byte = n*256 + ((k/8 ^ (n&7))*16) + (k&7)*2. Layout identical to SMEM.
__device__ __align__(16) __nv_bfloat16 g_WThi[320 * 128];
__device__ __align__(16) __nv_bfloat16 g_WTlo[320 * 128];

__device__ __forceinline__ float sigf(float x) {
    return 1.0f / (1.0f + expf(-x));
}
__device__ __forceinline__ void lstm1(float gi, float go, float gu, float gfl,
                                      float gfr, float cl, float cr,
                                      float& hh, float& cc) {
    cc = sigf(gi) * tanhf(gu) + sigf(gfl) * cl + sigf(gfr) * cr;
    hh = sigf(go) * tanhf(cc);
}
__device__ __forceinline__ uint32_t smem_u32(const void* p) {
    uint32_t a;
    asm("{ .reg .u64 t; cvta.to.shared.u64 t, %1; cvt.u32.u64 %0, t; }"
        : "=r"(a) : "l"(p));
    return a;
}
__device__ __forceinline__ uint32_t bf2hi(float x, float y) {
    __nv_bfloat16 hx = __float2bfloat16(x), hy = __float2bfloat16(y);
    return (uint32_t)__bfloat16_as_ushort(hx)
         | ((uint32_t)__bfloat16_as_ushort(hy) << 16);
}
__device__ __forceinline__ void ldsm4(uint32_t& r0, uint32_t& r1, uint32_t& r2,
                                      uint32_t& r3, uint32_t addr) {
    asm volatile("ldmatrix.sync.aligned.m8n8.x4.shared.b16 {%0,%1,%2,%3}, [%4];"
                 : "=r"(r0), "=r"(r1), "=r"(r2), "=r"(r3) : "r"(addr));
}
__device__ __forceinline__ void ldsm2(uint32_t& r0, uint32_t& r1, uint32_t addr) {
    asm volatile("ldmatrix.sync.aligned.m8n8.x2.shared.b16 {%0,%1}, [%2];"
                 : "=r"(r0), "=r"(r1) : "r"(addr));
}
__device__ __forceinline__ void mma16816(float* c, const uint32_t* a,
                                         const uint32_t* b) {
    asm volatile("mma.sync.aligned.m16n8k16.row.col.f32.bf16.bf16.f32 "
                 "{%0,%1,%2,%3}, {%4,%5,%6,%7}, {%8,%9}, {%0,%1,%2,%3};"
                 : "+f"(c[0]), "+f"(c[1]), "+f"(c[2]), "+f"(c[3])
                 : "r"(a[0]), "r"(a[1]), "r"(a[2]), "r"(a[3]),
                   "r"(b[0]), "r"(b[1]));
}

// ---- One-time weight prep: W^T, bf16 split, swizzled (matches smem) ----
__global__ void prep_w(const float* __restrict__ Wl, const float* __restrict__ Wr)
{
    int idx = blockIdx.x * blockDim.x + threadIdx.x;
    if (idx < 320 * 128) {
        int k = idx & 127;
        int n = idx >> 7;
        float w = (k < 64) ? Wl[k * G5 + n] : Wr[(k - 64) * G5 + n];
        __nv_bfloat16 hi = __float2bfloat16(w);
        __nv_bfloat16 lo = __float2bfloat16(w - __bfloat162float(hi));
        int byte = n * 256 + (((k >> 3) ^ (n & 7)) * 16) + (k & 7) * 2;
        g_WThi[byte >> 1] = hi;
        g_WTlo[byte >> 1] = lo;
    }
}

// ---- HMMA merge level: multi-tile blocks, 16 warps, rt-pair GEMM ----
__global__ __launch_bounds__(MMN, 1)
void merge_mma(const float* __restrict__ hb, const float* __restrict__ cb,
               int src_sel, int dst_sel,
               const float* __restrict__ bias, int n_out, int level)
{
    const float* h_src = (src_sel == 0) ? hb : (src_sel == 1 ? g_A_h : g_B_h);
    const float* c_src = (src_sel == 0) ? cb : (src_sel == 1 ? g_A_c : g_B_c);
    float* h_dst = (dst_sel == 1) ? g_A_h : g_B_h;
    float* c_dst = (dst_sel == 1) ? g_A_c : g_B_c;

    extern __shared__ __align__(1024) char sm[];
    const uint32_t smu = smem_u32(sm);
    const int tid = threadIdx.x;
    const int n_tiles = (n_out + MT - 1) / MT;

    if (blockIdx.x == 0 && tid < D) {
        int last = 2 * n_out - 1;
        g_lvl_h[level * D + tid] = h_src[(size_t)last * D + tid];
        g_lvl_c[level * D + tid] = c_src[(size_t)last * D + tid];
    }

    // ---- Copy pre-swizzled W^T (hi+lo) into smem ONCE per block ----
    {
        const uint4* wh = reinterpret_cast<const uint4*>(g_WThi);
        const uint4* wl = reinterpret_cast<const uint4*>(g_WTlo);
        uint4* dh = reinterpret_cast<uint4*>(sm + SM_WHI);
        uint4* dl = reinterpret_cast<uint4*>(sm + SM_WLO);
        for (int i = tid; i < 5120; i += MMN) {
            dh[i] = wh[i];
            dl[i] = wl[i];
        }
    }

    // Per-thread constants for the GEMM/epilogue phase.
    const int w    = tid >> 5;
    const int lane = tid & 31;
    const int gr   = lane >> 2;
    const int gc   = lane & 3;
    const int ct   = w & 7;            // n8 col tile within each 64 chunk
    const int rt0  = (w >> 3) * 4;     // warps 0-7 -> rt 0..3, 8-15 -> 4..7
    const int arl  = lane & 15;
    const int asel = lane >> 4;
    const int brl  = lane & 7;
    const int bsel = (lane >> 3) & 1;
    const int d0   = ct * 8 + gc * 2;

    float2 bi  = *reinterpret_cast<const float2*>(bias + 0 * D + d0);
    float2 bo  = *reinterpret_cast<const float2*>(bias + 1 * D + d0);
    float2 bu  = *reinterpret_cast<const float2*>(bias + 2 * D + d0);
    float2 bfl = *reinterpret_cast<const float2*>(bias + 3 * D + d0);
    float2 bfr = *reinterpret_cast<const float2*>(bias + 4 * D + d0);

    // Stage-phase constants.
    const int s_row  = tid & 127;      // cell row 0..127
    const int s_part = tid >> 7;       // 0..3
    const int s_half = s_part >> 1;    // 0 -> hl, 1 -> hr
    const int s_sub  = s_part & 1;     // jc quartet select

    for (int tile = blockIdx.x; tile < n_tiles; tile += gridDim.x) {
        const int cell0 = tile * MT;

        // ---- Stage X (bf16 hi/lo, swizzled 256B rows). 512 thr: 4 jc each ----
        {
            int cell = cell0 + s_row;
            bool valid = cell < n_out;
            const float4* src4 = reinterpret_cast<const float4*>(
                h_src + ((size_t)(2 * cell) + s_half) * D);
            char* bh = sm + SM_XHI + s_row * 256;
            char* bl = sm + SM_XLO + s_row * 256;
#pragma unroll
            for (int j = 0; j < 4; ++j) {
                int jc = s_sub * 4 + j;
                float4 a = make_float4(0.f, 0.f, 0.f, 0.f), b = a;
                if (valid) { a = src4[2 * jc]; b = src4[2 * jc + 1]; }
                uint4 hv, lv;
                hv.x = bf2hi(a.x, a.y); hv.y = bf2hi(a.z, a.w);
                hv.z = bf2hi(b.x, b.y); hv.w = bf2hi(b.z, b.w);
                float r0 = a.x - __bfloat162float(__float2bfloat16(a.x));
                float r1 = a.y - __bfloat162float(__float2bfloat16(a.y));
                float r2 = a.z - __bfloat162float(__float2bfloat16(a.z));
                float r3 = a.w - __bfloat162float(__float2bfloat16(a.w));
                float r4 = b.x - __bfloat162float(__float2bfloat16(b.x));
                float r5 = b.y - __bfloat162float(__float2bfloat16(b.y));
                float r6 = b.z - __bfloat162float(__float2bfloat16(b.z));
                float r7 = b.w - __bfloat162float(__float2bfloat16(b.w));
                lv.x = bf2hi(r0, r1); lv.y = bf2hi(r2, r3);
                lv.z = bf2hi(r4, r5); lv.w = bf2hi(r6, r7);
                int c16 = s_half * 8 + jc;
                int loc = ((c16 ^ (s_row & 7)) * 16);
                *reinterpret_cast<uint4*>(bh + loc) = hv;
                *reinterpret_cast<uint4*>(bl + loc) = lv;
            }
        }
        __syncthreads();

        // ---- Warp GEMM (rt pairs) + in-register LSTM epilogue ----
#pragma unroll
        for (int rtp = 0; rtp < 2; ++rtp) {
            const int rta = rt0 + 2 * rtp;   // this pair: rows rta, rta+1 (x16)
            float acc[2][5][4];
#pragma unroll
            for (int r = 0; r < 2; ++r)
#pragma unroll
                for (int g = 0; g < 5; ++g)
#pragma unroll
                    for (int q = 0; q < 4; ++q) acc[r][g][q] = 0.0f;

#pragma unroll
            for (int ks = 0; ks < 8; ++ks) {
                uint32_t ah[2][4], al[2][4];
#pragma unroll
                for (int r = 0; r < 2; ++r) {
                    uint32_t abase = ((rta + r) * 16 + arl) * 256;
                    uint32_t aswz = abase + (((2 * ks + asel) ^ (arl & 7)) * 16);
                    ldsm4(ah[r][0], ah[r][1], ah[r][2], ah[r][3], smu + SM_XHI + aswz);
                    ldsm4(al[r][0], al[r][1], al[r][2], al[r][3], smu + SM_XLO + aswz);
                }
#pragma unroll
                for (int g = 0; g < 5; ++g) {
                    uint32_t brow = g * 64 + ct * 8 + brl;
                    uint32_t bswz = brow * 256 + (((2 * ks + bsel) ^ brl) * 16);
                    uint32_t bh[2], bl[2];
                    ldsm2(bh[0], bh[1], smu + SM_WHI + bswz);
                    ldsm2(bl[0], bl[1], smu + SM_WLO + bswz);
#pragma unroll
                    for (int r = 0; r < 2; ++r) {
                        mma16816(acc[r][g], ah[r], bh);   // hi * hi
                        mma16816(acc[r][g], al[r], bh);   // lo * hi
                        mma16816(acc[r][g], ah[r], bl);   // hi * lo
                    }
                }
            }

#pragma unroll
            for (int r = 0; r < 2; ++r) {
                const int rt = rta + r;
#pragma unroll
                for (int half = 0; half < 2; ++half) {
                    int cell = cell0 + rt * 16 + gr + half * 8;
                    if (cell < n_out) {
                        int q = half * 2;
                        float2 cl = *reinterpret_cast<const float2*>(
                            c_src + (size_t)(2 * cell) * D + d0);
                        float2 cr = *reinterpret_cast<const float2*>(
                            c_src + (size_t)(2 * cell + 1) * D + d0);
                        float h0, c0, h1, c1;
                        lstm1(acc[r][0][q] + bi.x, acc[r][1][q] + bo.x,
                              acc[r][2][q] + bu.x, acc[r][3][q] + bfl.x,
                              acc[r][4][q] + bfr.x, cl.x, cr.x, h0, c0);
                        lstm1(acc[r][0][q+1] + bi.y, acc[r][1][q+1] + bo.y,
                              acc[r][2][q+1] + bu.y, acc[r][3][q+1] + bfl.y,
                              acc[r][4][q+1] + bfr.y, cl.y, cr.y, h1, c1);
                        *reinterpret_cast<float2*>(h_dst + (size_t)cell * D + d0) =
                            make_float2(h0, h1);
                        *reinterpret_cast<float2*>(c_dst + (size_t)cell * D + d0) =
                            make_float2(c0, c1);
                    }
                }
            }
        }
        __syncthreads();   // X smem consumed; safe to restage next tile
    }
}

// ---- Scalar fallback merge (proven R2/R7 design), used if opt-in smem fails --
__global__ __launch_bounds__(NTH, 3)
void merge_scalar(const float* __restrict__ hb, const float* __restrict__ cb,
                  int src_sel, int dst_sel,
                  const float* __restrict__ Wl, const float* __restrict__ Wr,
                  const float* __restrict__ b,
                  int n_out, int level)
{
    const float* h_src = (src_sel == 0) ? hb : (src_sel == 1 ? g_A_h : g_B_h);
    const float* c_src = (src_sel == 0) ? cb : (src_sel == 1 ? g_A_c : g_B_c);
    float* h_dst = (dst_sel == 1) ? g_A_h : g_B_h;
    float* c_dst = (dst_sel == 1) ? g_A_c : g_B_c;

    __shared__ __align__(16) float s_buf[CPB * G5];

    const int tid   = threadIdx.x;
    const int cell0 = blockIdx.x * CPB;
    const int ct    = tid % 80;
    const int cg    = tid / 80;

    float* s_h2 = s_buf;
    {
        const float4* src4 = reinterpret_cast<const float4*>(h_src) + (size_t)cell0 * 32;
        for (int idx = tid; idx < CPB * 2 * 16; idx += NTH) {
            int r  = idx >> 4;
            int f4 = idx & 15;
            int c  = r >> 1;
            int lr = r & 1;
            float4 v = make_float4(0.f, 0.f, 0.f, 0.f);
            if (cell0 + c < n_out) v = src4[idx];
            float* dst = s_h2 + c * 128 + 8 * f4 + lr;
            dst[0] = v.x; dst[2] = v.y; dst[4] = v.z; dst[6] = v.w;
        }
    }
    __syncthreads();

    const float4* wl4 = reinterpret_cast<const float4*>(Wl);
    const float4* wr4 = reinterpret_cast<const float4*>(Wr);
    float4 b4 = reinterpret_cast<const float4*>(b)[ct];

    float acc[8][4];
#pragma unroll
    for (int c = 0; c < 8; ++c) {
        acc[c][0] = b4.x; acc[c][1] = b4.y; acc[c][2] = b4.z; acc[c][3] = b4.w;
    }
    const float4* hbase = reinterpret_cast<const float4*>(s_h2) + (cg * 8) * 32;

#pragma unroll 2
    for (int k2 = 0; k2 < 32; ++k2) {
        float4 wl0 = wl4[(2 * k2    ) * 80 + ct];
        float4 wr0 = wr4[(2 * k2    ) * 80 + ct];
        float4 wl1 = wl4[(2 * k2 + 1) * 80 + ct];
        float4 wr1 = wr4[(2 * k2 + 1) * 80 + ct];
#pragma unroll
        for (int c = 0; c < 8; ++c) {
            float4 hv = hbase[c * 32 + k2];
            float a0 = acc[c][0], a1 = acc[c][1], a2 = acc[c][2], a3 = acc[c][3];
            a0 = fmaf(wl0.x, hv.x, a0); a1 = fmaf(wl0.y, hv.x, a1);
            a2 = fmaf(wl0.z, hv.x, a2); a3 = fmaf(wl0.w, hv.x, a3);
            a0 = fmaf(wr0.x, hv.y, a0); a1 = fmaf(wr0.y, hv.y, a1);
            a2 = fmaf(wr0.z, hv.y, a2); a3 = fmaf(wr0.w, hv.y, a3);
            a0 = fmaf(wl1.x, hv.z, a0); a1 = fmaf(wl1.y, hv.z, a1);
            a2 = fmaf(wl1.z, hv.z, a2); a3 = fmaf(wl1.w, hv.z, a3);
            a0 = fmaf(wr1.x, hv.w, a0); a1 = fmaf(wr1.y, hv.w, a1);
            a2 = fmaf(wr1.z, hv.w, a2); a3 = fmaf(wr1.w, hv.w, a3);
            acc[c][0] = a0; acc[c][1] = a1; acc[c][2] = a2; acc[c][3] = a3;
        }
    }
    __syncthreads();
#pragma unroll
    for (int c = 0; c < 8; ++c) {
        float4* p = reinterpret_cast<float4*>(s_buf + (cg * 8 + c) * G5) + ct;
        *p = make_float4(acc[c][0], acc[c][1], acc[c][2], acc[c][3]);
    }
    __syncthreads();

    for (int idx = tid; idx < CPB * D; idx += NTH) {
        int c = idx >> 6;
        int d = idx & 63;
        int cell = cell0 + c;
        if (cell < n_out) {
            const float* g = s_buf + c * G5;
            float cc, hh;
            lstm1(g[d], g[D + d], g[2 * D + d], g[3 * D + d], g[4 * D + d],
                  c_src[(size_t)(2 * cell) * D + d],
                  c_src[(size_t)(2 * cell + 1) * D + d], hh, cc);
            c_dst[(size_t)cell * D + d] = cc;
            h_dst[(size_t)cell * D + d] = hh;
        }
    }

    if (blockIdx.x == 0 && tid < D) {
        int last = 2 * n_out - 1;
        g_lvl_h[level * D + tid] = h_src[(size_t)last * D + tid];
        g_lvl_c[level * D + tid] = c_src[(size_t)last * D + tid];
    }
}

// ---- Single-block tail (n <= 64) + summary fold ----
__global__ __launch_bounds__(NTH)
void tail_kernel(const float* __restrict__ mWl, const float* __restrict__ mWr,
                 const float* __restrict__ mb,
                 const float* __restrict__ sWl, const float* __restrict__ sWr,
                 const float* __restrict__ sb,
                 int n_start, int src_sel, int level_start, int n_lvls_total,
                 float* __restrict__ out)
{
    __shared__ float s_h[64 * D];
    __shared__ float s_g[8 * G5];
    __shared__ float sh[D], sc2[D];

    const int tid = threadIdx.x;
    int n = n_start, src = src_sel, level = level_start;

    while (n > 1) {
        const float* h_src = (src == 1) ? g_A_h : g_B_h;
        const float* c_src = (src == 1) ? g_A_c : g_B_c;
        int dst = (level & 1) ? 2 : 1;
        float* h_dst = (dst == 1) ? g_A_h : g_B_h;
        float* c_dst = (dst == 1) ? g_A_c : g_B_c;

        if (tid < D) {
            g_lvl_h[level * D + tid] = h_src[(n - 1) * D + tid];
            g_lvl_c[level * D + tid] = c_src[(n - 1) * D + tid];
        }
        for (int i = tid; i < n * D; i += NTH) s_h[i] = h_src[i];
        __syncthreads();

        int n_out = n >> 1;
        for (int c0 = 0; c0 < n_out; c0 += 8) {
            float acc[8];
            float bv = mb[tid];
#pragma unroll
            for (int c = 0; c < 8; ++c) acc[c] = bv;
            for (int k = 0; k < D; ++k) {
                float wlv = mWl[k * G5 + tid];
                float wrv = mWr[k * G5 + tid];
#pragma unroll
                for (int c = 0; c < 8; ++c) {
                    int cell = c0 + c;
                    if (cell < n_out) {
                        acc[c] = fmaf(s_h[(2 * cell) * D + k], wlv, acc[c]);
                        acc[c] = fmaf(s_h[(2 * cell + 1) * D + k], wrv, acc[c]);
                    }
                }
            }
#pragma unroll
            for (int c = 0; c < 8; ++c) s_g[c * G5 + tid] = acc[c];
            __syncthreads();
            for (int idx = tid; idx < 8 * D; idx += NTH) {
                int c = idx >> 6;
                int d = idx & 63;
                int cell = c0 + c;
                if (cell < n_out) {
                    const float* g = s_g + c * G5;
                    float cc = sigf(g[d]) * tanhf(g[2 * D + d])
                             + sigf(g[3 * D + d]) * c_src[(2 * cell) * D + d]
                             + sigf(g[4 * D + d]) * c_src[(2 * cell + 1) * D + d];
                    float hh = sigf(g[D + d]) * tanhf(cc);
                    c_dst[cell * D + d] = cc;
                    h_dst[cell * D + d] = hh;
                }
            }
            __syncthreads();
        }
        n = n_out; src = dst; ++level;
    }

    {
        const float* rh = (src == 1) ? g_A_h : g_B_h;
        const float* rc = (src == 1) ? g_A_c : g_B_c;
        if (tid < D) { sh[tid] = rh[tid]; sc2[tid] = rc[tid]; }
        __syncthreads();

        for (int l = n_lvls_total - 1; l >= 0; --l) {
            const float* lh = g_lvl_h + l * D;
            float acc = sb[tid];
#pragma unroll 8
            for (int k = 0; k < D; ++k) {
                acc = fmaf(sh[k], sWl[k * G5 + tid], acc);
                acc = fmaf(lh[k], sWr[k * G5 + tid], acc);
            }
            s_g[tid] = acc;
            __syncthreads();
            if (tid < D) {
                const float* lc = g_lvl_c + l * D;
                float cc = sigf(s_g[tid]) * tanhf(s_g[2 * D + tid])
                         + sigf(s_g[3 * D + tid]) * sc2[tid]
                         + sigf(s_g[4 * D + tid]) * lc[tid];
                float hh = sigf(s_g[D + tid]) * tanhf(cc);
                sc2[tid] = cc;
                sh[tid] = hh;
            }
            __syncthreads();
        }
        if (tid < D) {
            out[tid]     = sh[tid];
            out[D + tid] = sc2[tid];
        }
    }
}

extern "C" void kernel_launch(void* const* d_in, const int* in_sizes, int n_in,
                              void* d_out, int out_size)
{
    const float* h_bot = (const float*)d_in[0];
    const float* c_bot = (const float*)d_in[1];
    const float* mWl   = (const float*)d_in[2];
    const float* mWr   = (const float*)d_in[3];
    const float* mb    = (const float*)d_in[4];
    const float* sWl   = (const float*)d_in[5];
    const float* sWr   = (const float*)d_in[6];
    const float* sb    = (const float*)d_in[7];

    cudaError_t attr_ok =
        cudaFuncSetAttribute(merge_mma, cudaFuncAttributeMaxDynamicSharedMemorySize,
                             SMEM_MM);
    bool use_mma = (attr_ok == cudaSuccess);

    if (use_mma) prep_w<<<(320 * 128 + 255) / 256, 256>>>(mWl, mWr);

    int n = in_sizes[0] / D;   // 524288
    int level = 0;
    int src_sel = 0;
    while (n >= 128) {
        int n_out = n >> 1;
        int dst_sel = (level & 1) ? 2 : 1;
        if (use_mma) {
            int tiles = (n_out + MT - 1) / MT;
            int grid = tiles < 148 ? tiles : 148;
            merge_mma<<<grid, MMN, SMEM_MM>>>(
                h_bot, c_bot, src_sel, dst_sel, mb, n_out, level);
        } else {
            merge_scalar<<<(n_out + CPB - 1) / CPB, NTH>>>(
                h_bot, c_bot, src_sel, dst_sel, mWl, mWr, mb, n_out, level);
        }
        src_sel = dst_sel;
        n = n_out;
        ++level;
    }
    int total = level;
    for (int m = n; m > 1; m >>= 1) ++total;
    tail_kernel<<<1, NTH>>>(mWl, mWr, mb, sWl, sWr, sb,
                            n, src_sel, level, total, (float*)d_out);
}

// round 16
// speedup vs baseline: 2.2746x; 1.2128x over previous
#include <cuda_runtime.h>
#include <cuda_bf16.h>
#include <math.h>
#include <stdint.h>

#define D    64
#define G5   320
#define MT   128            // cells per tile (GEMM M)
#define MMN  512            // threads in mma merge kernel (16 warps)
#define NTH  320            // tail / scalar threads
#define CPB  32             // scalar fallback: cells per block

// dynamic smem layout for merge_mma (bytes)
#define SM_XHI  0
#define SM_XLO  32768
#define SM_WHI  65536
#define SM_WLO  147456
#define SMEM_MM 229376      // 224 KB

// Scratch ping-pong buffers (allocation-free: __device__ globals).
__device__ __align__(16) float g_A_h[(1 << 18) * D];
__device__ __align__(16) float g_A_c[(1 << 18) * D];
__device__ __align__(16) float g_B_h[(1 << 17) * D];
__device__ __align__(16) float g_B_c[(1 << 17) * D];
// Per-level Fenwick representatives (last row of each level's INPUT), 19 levels.
__device__ float g_lvl_h[19 * D];
__device__ float g_lvl_c[19 * D];
// W^T = [Wl;Wr]^T as bf16 hi/lo, rows n=0..319, k=0..127, XOR-swizzled rows of
// 256B: byte = n*256 + ((k/8 ^ (n&7))*16) + (k&7)*2. Layout identical to SMEM.
__device__ __align__(16) __nv_bfloat16 g_WThi[320 * 128];
__device__ __align__(16) __nv_bfloat16 g_WTlo[320 * 128];

__device__ __forceinline__ float sigf(float x) {
    return 1.0f / (1.0f + expf(-x));
}
// Fast approx sigmoid/tanh: ex2.approx + rcp.approx (rel err ~1e-6).
__device__ __forceinline__ float fsig(float x) {
    float e, r;
    asm("ex2.approx.f32 %0, %1;" : "=f"(e) : "f"(x * -1.4426950408889634f));
    asm("rcp.approx.f32 %0, %1;" : "=f"(r) : "f"(1.0f + e));
    return r;
}
__device__ __forceinline__ float ftanh(float x) {
    return fmaf(2.0f, fsig(2.0f * x), -1.0f);
}
__device__ __forceinline__ void lstm1(float gi, float go, float gu, float gfl,
                                      float gfr, float cl, float cr,
                                      float& hh, float& cc) {
    cc = sigf(gi) * tanhf(gu) + sigf(gfl) * cl + sigf(gfr) * cr;
    hh = sigf(go) * tanhf(cc);
}
__device__ __forceinline__ void lstm1f(float gi, float go, float gu, float gfl,
                                       float gfr, float cl, float cr,
                                       float& hh, float& cc) {
    cc = fsig(gi) * ftanh(gu) + fsig(gfl) * cl + fsig(gfr) * cr;
    hh = fsig(go) * ftanh(cc);
}
__device__ __forceinline__ uint32_t smem_u32(const void* p) {
    uint32_t a;
    asm("{ .reg .u64 t; cvta.to.shared.u64 t, %1; cvt.u32.u64 %0, t; }"
        : "=r"(a) : "l"(p));
    return a;
}
__device__ __forceinline__ uint32_t bf2hi(float x, float y) {
    __nv_bfloat16 hx = __float2bfloat16(x), hy = __float2bfloat16(y);
    return (uint32_t)__bfloat16_as_ushort(hx)
         | ((uint32_t)__bfloat16_as_ushort(hy) << 16);
}
__device__ __forceinline__ void ldsm4(uint32_t& r0, uint32_t& r1, uint32_t& r2,
                                      uint32_t& r3, uint32_t addr) {
    asm volatile("ldmatrix.sync.aligned.m8n8.x4.shared.b16 {%0,%1,%2,%3}, [%4];"
                 : "=r"(r0), "=r"(r1), "=r"(r2), "=r"(r3) : "r"(addr));
}
__device__ __forceinline__ void ldsm2(uint32_t& r0, uint32_t& r1, uint32_t addr) {
    asm volatile("ldmatrix.sync.aligned.m8n8.x2.shared.b16 {%0,%1}, [%2];"
                 : "=r"(r0), "=r"(r1) : "r"(addr));
}
__device__ __forceinline__ void mma16816(float* c, const uint32_t* a,
                                         const uint32_t* b) {
    asm volatile("mma.sync.aligned.m16n8k16.row.col.f32.bf16.bf16.f32 "
                 "{%0,%1,%2,%3}, {%4,%5,%6,%7}, {%8,%9}, {%0,%1,%2,%3};"
                 : "+f"(c[0]), "+f"(c[1]), "+f"(c[2]), "+f"(c[3])
                 : "r"(a[0]), "r"(a[1]), "r"(a[2]), "r"(a[3]),
                   "r"(b[0]), "r"(b[1]));
}
#define BAR_GRP(id) asm volatile("bar.sync %0, 256;" :: "r"(id) : "memory")

// ---- One-time weight prep: W^T, bf16 split, swizzled (matches smem) ----
__global__ void prep_w(const float* __restrict__ Wl, const float* __restrict__ Wr)
{
    int idx = blockIdx.x * blockDim.x + threadIdx.x;
    if (idx < 320 * 128) {
        int k = idx & 127;
        int n = idx >> 7;
        float w = (k < 64) ? Wl[k * G5 + n] : Wr[(k - 64) * G5 + n];
        __nv_bfloat16 hi = __float2bfloat16(w);
        __nv_bfloat16 lo = __float2bfloat16(w - __bfloat162float(hi));
        int byte = n * 256 + (((k >> 3) ^ (n & 7)) * 16) + (k & 7) * 2;
        g_WThi[byte >> 1] = hi;
        g_WTlo[byte >> 1] = lo;
    }
}

// ---- HMMA merge level: two independent 256-thread half-tile engines ----
__global__ __launch_bounds__(MMN, 1)
void merge_mma(const float* __restrict__ hb, const float* __restrict__ cb,
               int src_sel, int dst_sel,
               const float* __restrict__ bias, int n_out, int level)
{
    const float* h_src = (src_sel == 0) ? hb : (src_sel == 1 ? g_A_h : g_B_h);
    const float* c_src = (src_sel == 0) ? cb : (src_sel == 1 ? g_A_c : g_B_c);
    float* h_dst = (dst_sel == 1) ? g_A_h : g_B_h;
    float* c_dst = (dst_sel == 1) ? g_A_c : g_B_c;

    extern __shared__ __align__(1024) char sm[];
    const uint32_t smu = smem_u32(sm);
    const int tid = threadIdx.x;
    const int n_tiles = (n_out + MT - 1) / MT;

    if (blockIdx.x == 0 && tid < D) {
        int last = 2 * n_out - 1;
        g_lvl_h[level * D + tid] = h_src[(size_t)last * D + tid];
        g_lvl_c[level * D + tid] = c_src[(size_t)last * D + tid];
    }

    // ---- Copy pre-swizzled W^T (hi+lo) into smem ONCE per block ----
    {
        const uint4* wh = reinterpret_cast<const uint4*>(g_WThi);
        const uint4* wl = reinterpret_cast<const uint4*>(g_WTlo);
        uint4* dh = reinterpret_cast<uint4*>(sm + SM_WHI);
        uint4* dl = reinterpret_cast<uint4*>(sm + SM_WLO);
        for (int i = tid; i < 5120; i += MMN) {
            dh[i] = wh[i];
            dl[i] = wl[i];
        }
    }
    __syncthreads();   // W visible to all; after this the two groups never meet

    // Group split: group 0 = warps 0-7 (rows 0-63, rt 0-3); group 1 = warps
    // 8-15 (rows 64-127, rt 4-7). X halves are disjoint in smem.
    const int group = tid >> 8;        // 0 or 1
    const int gtid  = tid & 255;
    const int barid = 1 + group;

    // GEMM/epilogue constants.
    const int w    = tid >> 5;
    const int lane = tid & 31;
    const int gr   = lane >> 2;
    const int gc   = lane & 3;
    const int ct   = w & 7;            // n8 col tile within each 64 chunk
    const int rtb  = group * 4;        // rt base for this group
    const int arl  = lane & 15;
    const int asel = lane >> 4;
    const int brl  = lane & 7;
    const int bsel = (lane >> 3) & 1;
    const int d0   = ct * 8 + gc * 2;

    float2 bi  = *reinterpret_cast<const float2*>(bias + 0 * D + d0);
    float2 bo  = *reinterpret_cast<const float2*>(bias + 1 * D + d0);
    float2 bu  = *reinterpret_cast<const float2*>(bias + 2 * D + d0);
    float2 bfl = *reinterpret_cast<const float2*>(bias + 3 * D + d0);
    float2 bfr = *reinterpret_cast<const float2*>(bias + 4 * D + d0);

    // Stage-phase constants (per group: 256 threads stage 64 rows).
    const int s_row  = group * 64 + (gtid >> 2);   // this thread's X row
    const int s_part = gtid & 3;
    const int s_half = s_part >> 1;    // 0 -> hl, 1 -> hr
    const int s_sub  = s_part & 1;     // jc quartet select

    for (int tile = blockIdx.x; tile < n_tiles; tile += gridDim.x) {
        const int cell0 = tile * MT;

        // ---- Stage this group's X half (bf16 hi/lo, swizzled 256B rows) ----
        {
            int cell = cell0 + s_row;
            bool valid = cell < n_out;
            const float4* src4 = reinterpret_cast<const float4*>(
                h_src + ((size_t)(2 * cell) + s_half) * D);
            char* bh = sm + SM_XHI + s_row * 256;
            char* bl = sm + SM_XLO + s_row * 256;
#pragma unroll
            for (int j = 0; j < 4; ++j) {
                int jc = s_sub * 4 + j;
                float4 a = make_float4(0.f, 0.f, 0.f, 0.f), b = a;
                if (valid) { a = src4[2 * jc]; b = src4[2 * jc + 1]; }
                uint4 hv, lv;
                hv.x = bf2hi(a.x, a.y); hv.y = bf2hi(a.z, a.w);
                hv.z = bf2hi(b.x, b.y); hv.w = bf2hi(b.z, b.w);
                float r0 = a.x - __bfloat162float(__float2bfloat16(a.x));
                float r1 = a.y - __bfloat162float(__float2bfloat16(a.y));
                float r2 = a.z - __bfloat162float(__float2bfloat16(a.z));
                float r3 = a.w - __bfloat162float(__float2bfloat16(a.w));
                float r4 = b.x - __bfloat162float(__float2bfloat16(b.x));
                float r5 = b.y - __bfloat162float(__float2bfloat16(b.y));
                float r6 = b.z - __bfloat162float(__float2bfloat16(b.z));
                float r7 = b.w - __bfloat162float(__float2bfloat16(b.w));
                lv.x = bf2hi(r0, r1); lv.y = bf2hi(r2, r3);
                lv.z = bf2hi(r4, r5); lv.w = bf2hi(r6, r7);
                int c16 = s_half * 8 + jc;
                int loc = ((c16 ^ (s_row & 7)) * 16);
                *reinterpret_cast<uint4*>(bh + loc) = hv;
                *reinterpret_cast<uint4*>(bl + loc) = lv;
            }
        }
        BAR_GRP(barid);

        // ---- Warp GEMM + epilogue over this group's 4 rt tiles ----
        for (int rt = rtb; rt < rtb + 4; ++rt) {
            // Prefetch c inputs for this rt (hidden under the MMA chain).
            int cellA = cell0 + rt * 16 + gr;       // half 0
            int cellB = cellA + 8;                  // half 1
            bool vA = cellA < n_out, vB = cellB < n_out;
            float2 clA = make_float2(0.f, 0.f), crA = clA, clB = clA, crB = clA;
            if (vA) {
                clA = *reinterpret_cast<const float2*>(
                    c_src + (size_t)(2 * cellA) * D + d0);
                crA = *reinterpret_cast<const float2*>(
                    c_src + (size_t)(2 * cellA + 1) * D + d0);
            }
            if (vB) {
                clB = *reinterpret_cast<const float2*>(
                    c_src + (size_t)(2 * cellB) * D + d0);
                crB = *reinterpret_cast<const float2*>(
                    c_src + (size_t)(2 * cellB + 1) * D + d0);
            }

            float acc[5][4];
#pragma unroll
            for (int g = 0; g < 5; ++g)
#pragma unroll
                for (int q = 0; q < 4; ++q) acc[g][q] = 0.0f;

            const uint32_t abase = (rt * 16 + arl) * 256;
#pragma unroll
            for (int ks = 0; ks < 8; ++ks) {
                uint32_t aswz = abase + (((2 * ks + asel) ^ (arl & 7)) * 16);
                uint32_t ah[4], al[4];
                ldsm4(ah[0], ah[1], ah[2], ah[3], smu + SM_XHI + aswz);
                ldsm4(al[0], al[1], al[2], al[3], smu + SM_XLO + aswz);
#pragma unroll
                for (int g = 0; g < 5; ++g) {
                    uint32_t brow = g * 64 + ct * 8 + brl;
                    uint32_t bswz = brow * 256 + (((2 * ks + bsel) ^ brl) * 16);
                    uint32_t bh[2], bl[2];
                    ldsm2(bh[0], bh[1], smu + SM_WHI + bswz);
                    ldsm2(bl[0], bl[1], smu + SM_WLO + bswz);
                    mma16816(acc[g], ah, bh);   // hi * hi
                    mma16816(acc[g], al, bh);   // lo * hi
                    mma16816(acc[g], ah, bl);   // hi * lo
                }
            }

            if (vA) {
                float h0, c0, h1, c1;
                lstm1f(acc[0][0] + bi.x, acc[1][0] + bo.x, acc[2][0] + bu.x,
                       acc[3][0] + bfl.x, acc[4][0] + bfr.x, clA.x, crA.x, h0, c0);
                lstm1f(acc[0][1] + bi.y, acc[1][1] + bo.y, acc[2][1] + bu.y,
                       acc[3][1] + bfl.y, acc[4][1] + bfr.y, clA.y, crA.y, h1, c1);
                *reinterpret_cast<float2*>(h_dst + (size_t)cellA * D + d0) =
                    make_float2(h0, h1);
                *reinterpret_cast<float2*>(c_dst + (size_t)cellA * D + d0) =
                    make_float2(c0, c1);
            }
            if (vB) {
                float h0, c0, h1, c1;
                lstm1f(acc[0][2] + bi.x, acc[1][2] + bo.x, acc[2][2] + bu.x,
                       acc[3][2] + bfl.x, acc[4][2] + bfr.x, clB.x, crB.x, h0, c0);
                lstm1f(acc[0][3] + bi.y, acc[1][3] + bo.y, acc[2][3] + bu.y,
                       acc[3][3] + bfl.y, acc[4][3] + bfr.y, clB.y, crB.y, h1, c1);
                *reinterpret_cast<float2*>(h_dst + (size_t)cellB * D + d0) =
                    make_float2(h0, h1);
                *reinterpret_cast<float2*>(c_dst + (size_t)cellB * D + d0) =
                    make_float2(c0, c1);
            }
        }
        BAR_GRP(barid);   // group's X half consumed; safe to restage
    }
}

// ---- Scalar fallback merge (proven R2/R7 design), used if opt-in smem fails --
__global__ __launch_bounds__(NTH, 3)
void merge_scalar(const float* __restrict__ hb, const float* __restrict__ cb,
                  int src_sel, int dst_sel,
                  const float* __restrict__ Wl, const float* __restrict__ Wr,
                  const float* __restrict__ b,
                  int n_out, int level)
{
    const float* h_src = (src_sel == 0) ? hb : (src_sel == 1 ? g_A_h : g_B_h);
    const float* c_src = (src_sel == 0) ? cb : (src_sel == 1 ? g_A_c : g_B_c);
    float* h_dst = (dst_sel == 1) ? g_A_h : g_B_h;
    float* c_dst = (dst_sel == 1) ? g_A_c : g_B_c;

    __shared__ __align__(16) float s_buf[CPB * G5];

    const int tid   = threadIdx.x;
    const int cell0 = blockIdx.x * CPB;
    const int ct    = tid % 80;
    const int cg    = tid / 80;

    float* s_h2 = s_buf;
    {
        const float4* src4 = reinterpret_cast<const float4*>(h_src) + (size_t)cell0 * 32;
        for (int idx = tid; idx < CPB * 2 * 16; idx += NTH) {
            int r  = idx >> 4;
            int f4 = idx & 15;
            int c  = r >> 1;
            int lr = r & 1;
            float4 v = make_float4(0.f, 0.f, 0.f, 0.f);
            if (cell0 + c < n_out) v = src4[idx];
            float* dst = s_h2 + c * 128 + 8 * f4 + lr;
            dst[0] = v.x; dst[2] = v.y; dst[4] = v.z; dst[6] = v.w;
        }
    }
    __syncthreads();

    const float4* wl4 = reinterpret_cast<const float4*>(Wl);
    const float4* wr4 = reinterpret_cast<const float4*>(Wr);
    float4 b4 = reinterpret_cast<const float4*>(b)[ct];

    float acc[8][4];
#pragma unroll
    for (int c = 0; c < 8; ++c) {
        acc[c][0] = b4.x; acc[c][1] = b4.y; acc[c][2] = b4.z; acc[c][3] = b4.w;
    }
    const float4* hbase = reinterpret_cast<const float4*>(s_h2) + (cg * 8) * 32;

#pragma unroll 2
    for (int k2 = 0; k2 < 32; ++k2) {
        float4 wl0 = wl4[(2 * k2    ) * 80 + ct];
        float4 wr0 = wr4[(2 * k2    ) * 80 + ct];
        float4 wl1 = wl4[(2 * k2 + 1) * 80 + ct];
        float4 wr1 = wr4[(2 * k2 + 1) * 80 + ct];
#pragma unroll
        for (int c = 0; c < 8; ++c) {
            float4 hv = hbase[c * 32 + k2];
            float a0 = acc[c][0], a1 = acc[c][1], a2 = acc[c][2], a3 = acc[c][3];
            a0 = fmaf(wl0.x, hv.x, a0); a1 = fmaf(wl0.y, hv.x, a1);
            a2 = fmaf(wl0.z, hv.x, a2); a3 = fmaf(wl0.w, hv.x, a3);
            a0 = fmaf(wr0.x, hv.y, a0); a1 = fmaf(wr0.y, hv.y, a1);
            a2 = fmaf(wr0.z, hv.y, a2); a3 = fmaf(wr0.w, hv.y, a3);
            a0 = fmaf(wl1.x, hv.z, a0); a1 = fmaf(wl1.y, hv.z, a1);
            a2 = fmaf(wl1.z, hv.z, a2); a3 = fmaf(wl1.w, hv.z, a3);
            a0 = fmaf(wr1.x, hv.w, a0); a1 = fmaf(wr1.y, hv.w, a1);
            a2 = fmaf(wr1.z, hv.w, a2); a3 = fmaf(wr1.w, hv.w, a3);
            acc[c][0] = a0; acc[c][1] = a1; acc[c][2] = a2; acc[c][3] = a3;
        }
    }
    __syncthreads();
#pragma unroll
    for (int c = 0; c < 8; ++c) {
        float4* p = reinterpret_cast<float4*>(s_buf + (cg * 8 + c) * G5) + ct;
        *p = make_float4(acc[c][0], acc[c][1], acc[c][2], acc[c][3]);
    }
    __syncthreads();

    for (int idx = tid; idx < CPB * D; idx += NTH) {
        int c = idx >> 6;
        int d = idx & 63;
        int cell = cell0 + c;
        if (cell < n_out) {
            const float* g = s_buf + c * G5;
            float cc, hh;
            lstm1(g[d], g[D + d], g[2 * D + d], g[3 * D + d], g[4 * D + d],
                  c_src[(size_t)(2 * cell) * D + d],
                  c_src[(size_t)(2 * cell + 1) * D + d], hh, cc);
            c_dst[(size_t)cell * D + d] = cc;
            h_dst[(size_t)cell * D + d] = hh;
        }
    }

    if (blockIdx.x == 0 && tid < D) {
        int last = 2 * n_out - 1;
        g_lvl_h[level * D + tid] = h_src[(size_t)last * D + tid];
        g_lvl_c[level * D + tid] = c_src[(size_t)last * D + tid];
    }
}

// ---- Single-block tail (n <= 64) + summary fold ----
__global__ __launch_bounds__(NTH)
void tail_kernel(const float* __restrict__ mWl, const float* __restrict__ mWr,
                 const float* __restrict__ mb,
                 const float* __restrict__ sWl, const float* __restrict__ sWr,
                 const float* __restrict__ sb,
                 int n_start, int src_sel, int level_start, int n_lvls_total,
                 float* __restrict__ out)
{
    __shared__ float s_h[64 * D];
    __shared__ float s_g[8 * G5];
    __shared__ float sh[D], sc2[D];

    const int tid = threadIdx.x;
    int n = n_start, src = src_sel, level = level_start;

    while (n > 1) {
        const float* h_src = (src == 1) ? g_A_h : g_B_h;
        const float* c_src = (src == 1) ? g_A_c : g_B_c;
        int dst = (level & 1) ? 2 : 1;
        float* h_dst = (dst == 1) ? g_A_h : g_B_h;
        float* c_dst = (dst == 1) ? g_A_c : g_B_c;

        if (tid < D) {
            g_lvl_h[level * D + tid] = h_src[(n - 1) * D + tid];
            g_lvl_c[level * D + tid] = c_src[(n - 1) * D + tid];
        }
        for (int i = tid; i < n * D; i += NTH) s_h[i] = h_src[i];
        __syncthreads();

        int n_out = n >> 1;
        for (int c0 = 0; c0 < n_out; c0 += 8) {
            float acc[8];
            float bv = mb[tid];
#pragma unroll
            for (int c = 0; c < 8; ++c) acc[c] = bv;
            for (int k = 0; k < D; ++k) {
                float wlv = mWl[k * G5 + tid];
                float wrv = mWr[k * G5 + tid];
#pragma unroll
                for (int c = 0; c < 8; ++c) {
                    int cell = c0 + c;
                    if (cell < n_out) {
                        acc[c] = fmaf(s_h[(2 * cell) * D + k], wlv, acc[c]);
                        acc[c] = fmaf(s_h[(2 * cell + 1) * D + k], wrv, acc[c]);
                    }
                }
            }
#pragma unroll
            for (int c = 0; c < 8; ++c) s_g[c * G5 + tid] = acc[c];
            __syncthreads();
            for (int idx = tid; idx < 8 * D; idx += NTH) {
                int c = idx >> 6;
                int d = idx & 63;
                int cell = c0 + c;
                if (cell < n_out) {
                    const float* g = s_g + c * G5;
                    float cc = sigf(g[d]) * tanhf(g[2 * D + d])
                             + sigf(g[3 * D + d]) * c_src[(2 * cell) * D + d]
                             + sigf(g[4 * D + d]) * c_src[(2 * cell + 1) * D + d];
                    float hh = sigf(g[D + d]) * tanhf(cc);
                    c_dst[cell * D + d] = cc;
                    h_dst[cell * D + d] = hh;
                }
            }
            __syncthreads();
        }
        n = n_out; src = dst; ++level;
    }

    {
        const float* rh = (src == 1) ? g_A_h : g_B_h;
        const float* rc = (src == 1) ? g_A_c : g_B_c;
        if (tid < D) { sh[tid] = rh[tid]; sc2[tid] = rc[tid]; }
        __syncthreads();

        for (int l = n_lvls_total - 1; l >= 0; --l) {
            const float* lh = g_lvl_h + l * D;
            float acc = sb[tid];
#pragma unroll 8
            for (int k = 0; k < D; ++k) {
                acc = fmaf(sh[k], sWl[k * G5 + tid], acc);
                acc = fmaf(lh[k], sWr[k * G5 + tid], acc);
            }
            s_g[tid] = acc;
            __syncthreads();
            if (tid < D) {
                const float* lc = g_lvl_c + l * D;
                float cc = sigf(s_g[tid]) * tanhf(s_g[2 * D + tid])
                         + sigf(s_g[3 * D + tid]) * sc2[tid]
                         + sigf(s_g[4 * D + tid]) * lc[tid];
                float hh = sigf(s_g[D + tid]) * tanhf(cc);
                sc2[tid] = cc;
                sh[tid] = hh;
            }
            __syncthreads();
        }
        if (tid < D) {
            out[tid]     = sh[tid];
            out[D + tid] = sc2[tid];
        }
    }
}

extern "C" void kernel_launch(void* const* d_in, const int* in_sizes, int n_in,
                              void* d_out, int out_size)
{
    const float* h_bot = (const float*)d_in[0];
    const float* c_bot = (const float*)d_in[1];
    const float* mWl   = (const float*)d_in[2];
    const float* mWr   = (const float*)d_in[3];
    const float* mb    = (const float*)d_in[4];
    const float* sWl   = (const float*)d_in[5];
    const float* sWr   = (const float*)d_in[6];
    const float* sb    = (const float*)d_in[7];

    cudaError_t attr_ok =
        cudaFuncSetAttribute(merge_mma, cudaFuncAttributeMaxDynamicSharedMemorySize,
                             SMEM_MM);
    bool use_mma = (attr_ok == cudaSuccess);

    if (use_mma) prep_w<<<(320 * 128 + 255) / 256, 256>>>(mWl, mWr);

    int n = in_sizes[0] / D;   // 524288
    int level = 0;
    int src_sel = 0;
    while (n >= 128) {
        int n_out = n >> 1;
        int dst_sel = (level & 1) ? 2 : 1;
        if (use_mma) {
            int tiles = (n_out + MT - 1) / MT;
            int grid = tiles < 148 ? tiles : 148;
            merge_mma<<<grid, MMN, SMEM_MM>>>(
                h_bot, c_bot, src_sel, dst_sel, mb, n_out, level);
        } else {
            merge_scalar<<<(n_out + CPB - 1) / CPB, NTH>>>(
                h_bot, c_bot, src_sel, dst_sel, mWl, mWr, mb, n_out, level);
        }
        src_sel = dst_sel;
        n = n_out;
        ++level;
    }
    int total = level;
    for (int m = n; m > 1; m >>= 1) ++total;
    tail_kernel<<<1, NTH>>>(mWl, mWr, mb, sWl, sWr, sb,
                            n, src_sel, level, total, (float*)d_out);
}

// round 17
// speedup vs baseline: 2.5749x; 1.1320x over previous
#include <cuda_runtime.h>
#include <cuda_fp16.h>
#include <math.h>
#include <stdint.h>

#define D    64
#define G5   320
#define MT   128            // cells per tile (GEMM M)
#define MMN  512            // threads in mma merge kernel (16 warps)
#define NTH  320            // tail / scalar threads
#define CPB  32             // scalar fallback: cells per block

// dynamic smem layout for merge_mma (bytes)
#define SM_XHI  0
#define SM_XLO  32768
#define SM_W    65536
#define SMEM_MM 147456      // 144 KB

// Scratch ping-pong buffers (allocation-free: __device__ globals).
__device__ __align__(16) float g_A_h[(1 << 18) * D];
__device__ __align__(16) float g_A_c[(1 << 18) * D];
__device__ __align__(16) float g_B_h[(1 << 17) * D];
__device__ __align__(16) float g_B_c[(1 << 17) * D];
// Per-level Fenwick representatives (last row of each level's INPUT), 19 levels.
__device__ float g_lvl_h[19 * D];
__device__ float g_lvl_c[19 * D];
// W^T = [Wl;Wr]^T as single fp16, rows n=0..319, k=0..127, XOR-swizzled rows of
// 256B: byte = n*256 + ((k/8 ^ (n&7))*16) + (k&7)*2. Layout identical to SMEM.
__device__ __align__(16) __half g_WT[320 * 128];

__device__ __forceinline__ float sigf(float x) {
    return 1.0f / (1.0f + expf(-x));
}
// Fast approx sigmoid/tanh: ex2.approx + rcp.approx (rel err ~1e-6).
__device__ __forceinline__ float fsig(float x) {
    float e, r;
    asm("ex2.approx.f32 %0, %1;" : "=f"(e) : "f"(x * -1.4426950408889634f));
    asm("rcp.approx.f32 %0, %1;" : "=f"(r) : "f"(1.0f + e));
    return r;
}
__device__ __forceinline__ float ftanh(float x) {
    return fmaf(2.0f, fsig(2.0f * x), -1.0f);
}
__device__ __forceinline__ void lstm1(float gi, float go, float gu, float gfl,
                                      float gfr, float cl, float cr,
                                      float& hh, float& cc) {
    cc = sigf(gi) * tanhf(gu) + sigf(gfl) * cl + sigf(gfr) * cr;
    hh = sigf(go) * tanhf(cc);
}
__device__ __forceinline__ void lstm1f(float gi, float go, float gu, float gfl,
                                       float gfr, float cl, float cr,
                                       float& hh, float& cc) {
    cc = fsig(gi) * ftanh(gu) + fsig(gfl) * cl + fsig(gfr) * cr;
    hh = fsig(go) * ftanh(cc);
}
__device__ __forceinline__ uint32_t smem_u32(const void* p) {
    uint32_t a;
    asm("{ .reg .u64 t; cvta.to.shared.u64 t, %1; cvt.u32.u64 %0, t; }"
        : "=r"(a) : "l"(p));
    return a;
}
__device__ __forceinline__ uint32_t h2pack(float x, float y) {
    __half hx = __float2half_rn(x), hy = __float2half_rn(y);
    return (uint32_t)__half_as_ushort(hx)
         | ((uint32_t)__half_as_ushort(hy) << 16);
}
__device__ __forceinline__ void ldsm4(uint32_t& r0, uint32_t& r1, uint32_t& r2,
                                      uint32_t& r3, uint32_t addr) {
    asm volatile("ldmatrix.sync.aligned.m8n8.x4.shared.b16 {%0,%1,%2,%3}, [%4];"
                 : "=r"(r0), "=r"(r1), "=r"(r2), "=r"(r3) : "r"(addr));
}
__device__ __forceinline__ void ldsm2(uint32_t& r0, uint32_t& r1, uint32_t addr) {
    asm volatile("ldmatrix.sync.aligned.m8n8.x2.shared.b16 {%0,%1}, [%2];"
                 : "=r"(r0), "=r"(r1) : "r"(addr));
}
__device__ __forceinline__ void mma16816h(float* c, const uint32_t* a,
                                          const uint32_t* b) {
    asm volatile("mma.sync.aligned.m16n8k16.row.col.f32.f16.f16.f32 "
                 "{%0,%1,%2,%3}, {%4,%5,%6,%7}, {%8,%9}, {%0,%1,%2,%3};"
                 : "+f"(c[0]), "+f"(c[1]), "+f"(c[2]), "+f"(c[3])
                 : "r"(a[0]), "r"(a[1]), "r"(a[2]), "r"(a[3]),
                   "r"(b[0]), "r"(b[1]));
}
#define BAR_GRP(id) asm volatile("bar.sync %0, 256;" :: "r"(id) : "memory")

// ---- One-time weight prep: W^T, single fp16, swizzled (matches smem) ----
__global__ void prep_w(const float* __restrict__ Wl, const float* __restrict__ Wr)
{
    int idx = blockIdx.x * blockDim.x + threadIdx.x;
    if (idx < 320 * 128) {
        int k = idx & 127;
        int n = idx >> 7;
        float w = (k < 64) ? Wl[k * G5 + n] : Wr[(k - 64) * G5 + n];
        int byte = n * 256 + (((k >> 3) ^ (n & 7)) * 16) + (k & 7) * 2;
        g_WT[byte >> 1] = __float2half_rn(w);
    }
}

// ---- HMMA merge level: two independent 256-thread half-tile engines,
// ---- fp16 2-term split (A = hi+lo fp16, B = single fp16) ----
__global__ __launch_bounds__(MMN, 1)
void merge_mma(const float* __restrict__ hb, const float* __restrict__ cb,
               int src_sel, int dst_sel,
               const float* __restrict__ bias, int n_out, int level)
{
    const float* h_src = (src_sel == 0) ? hb : (src_sel == 1 ? g_A_h : g_B_h);
    const float* c_src = (src_sel == 0) ? cb : (src_sel == 1 ? g_A_c : g_B_c);
    float* h_dst = (dst_sel == 1) ? g_A_h : g_B_h;
    float* c_dst = (dst_sel == 1) ? g_A_c : g_B_c;

    extern __shared__ __align__(1024) char sm[];
    const uint32_t smu = smem_u32(sm);
    const int tid = threadIdx.x;
    const int n_tiles = (n_out + MT - 1) / MT;

    if (blockIdx.x == 0 && tid < D) {
        int last = 2 * n_out - 1;
        g_lvl_h[level * D + tid] = h_src[(size_t)last * D + tid];
        g_lvl_c[level * D + tid] = c_src[(size_t)last * D + tid];
    }

    // ---- Copy pre-swizzled W^T into smem ONCE per block (80 KB) ----
    {
        const uint4* wp = reinterpret_cast<const uint4*>(g_WT);
        uint4* dw = reinterpret_cast<uint4*>(sm + SM_W);
        for (int i = tid; i < 5120; i += MMN) dw[i] = wp[i];
    }
    __syncthreads();   // W visible to all; after this the two groups never meet

    // Group split: group 0 = warps 0-7 (rows 0-63, rt 0-3); group 1 = warps
    // 8-15 (rows 64-127, rt 4-7). X halves are disjoint in smem.
    const int group = tid >> 8;        // 0 or 1
    const int gtid  = tid & 255;
    const int barid = 1 + group;

    // GEMM/epilogue constants.
    const int w    = tid >> 5;
    const int lane = tid & 31;
    const int gr   = lane >> 2;
    const int gc   = lane & 3;
    const int ct   = w & 7;            // n8 col tile within each 64 chunk
    const int rtb  = group * 4;        // rt base for this group
    const int arl  = lane & 15;
    const int asel = lane >> 4;
    const int brl  = lane & 7;
    const int bsel = (lane >> 3) & 1;
    const int d0   = ct * 8 + gc * 2;

    float2 bi  = *reinterpret_cast<const float2*>(bias + 0 * D + d0);
    float2 bo  = *reinterpret_cast<const float2*>(bias + 1 * D + d0);
    float2 bu  = *reinterpret_cast<const float2*>(bias + 2 * D + d0);
    float2 bfl = *reinterpret_cast<const float2*>(bias + 3 * D + d0);
    float2 bfr = *reinterpret_cast<const float2*>(bias + 4 * D + d0);

    // Stage-phase constants (per group: 256 threads stage 64 rows).
    const int s_row  = group * 64 + (gtid >> 2);   // this thread's X row
    const int s_part = gtid & 3;
    const int s_half = s_part >> 1;    // 0 -> hl, 1 -> hr
    const int s_sub  = s_part & 1;     // jc quartet select

    for (int tile = blockIdx.x; tile < n_tiles; tile += gridDim.x) {
        const int cell0 = tile * MT;

        // ---- Stage this group's X half (fp16 hi/lo, swizzled 256B rows) ----
        {
            int cell = cell0 + s_row;
            bool valid = cell < n_out;
            const float4* src4 = reinterpret_cast<const float4*>(
                h_src + ((size_t)(2 * cell) + s_half) * D);
            char* bh = sm + SM_XHI + s_row * 256;
            char* bl = sm + SM_XLO + s_row * 256;
#pragma unroll
            for (int j = 0; j < 4; ++j) {
                int jc = s_sub * 4 + j;
                float4 a = make_float4(0.f, 0.f, 0.f, 0.f), b = a;
                if (valid) { a = src4[2 * jc]; b = src4[2 * jc + 1]; }
                uint4 hv, lv;
                hv.x = h2pack(a.x, a.y); hv.y = h2pack(a.z, a.w);
                hv.z = h2pack(b.x, b.y); hv.w = h2pack(b.z, b.w);
                float r0 = a.x - __half2float(__float2half_rn(a.x));
                float r1 = a.y - __half2float(__float2half_rn(a.y));
                float r2 = a.z - __half2float(__float2half_rn(a.z));
                float r3 = a.w - __half2float(__float2half_rn(a.w));
                float r4 = b.x - __half2float(__float2half_rn(b.x));
                float r5 = b.y - __half2float(__float2half_rn(b.y));
                float r6 = b.z - __half2float(__float2half_rn(b.z));
                float r7 = b.w - __half2float(__float2half_rn(b.w));
                lv.x = h2pack(r0, r1); lv.y = h2pack(r2, r3);
                lv.z = h2pack(r4, r5); lv.w = h2pack(r6, r7);
                int c16 = s_half * 8 + jc;
                int loc = ((c16 ^ (s_row & 7)) * 16);
                *reinterpret_cast<uint4*>(bh + loc) = hv;
                *reinterpret_cast<uint4*>(bl + loc) = lv;
            }
        }
        BAR_GRP(barid);

        // ---- Warp GEMM + epilogue over this group's 4 rt tiles ----
        for (int rt = rtb; rt < rtb + 4; ++rt) {
            // Prefetch c inputs for this rt (hidden under the MMA chain).
            int cellA = cell0 + rt * 16 + gr;       // half 0
            int cellB = cellA + 8;                  // half 1
            bool vA = cellA < n_out, vB = cellB < n_out;
            float2 clA = make_float2(0.f, 0.f), crA = clA, clB = clA, crB = clA;
            if (vA) {
                clA = *reinterpret_cast<const float2*>(
                    c_src + (size_t)(2 * cellA) * D + d0);
                crA = *reinterpret_cast<const float2*>(
                    c_src + (size_t)(2 * cellA + 1) * D + d0);
            }
            if (vB) {
                clB = *reinterpret_cast<const float2*>(
                    c_src + (size_t)(2 * cellB) * D + d0);
                crB = *reinterpret_cast<const float2*>(
                    c_src + (size_t)(2 * cellB + 1) * D + d0);
            }

            float acc[5][4];
#pragma unroll
            for (int g = 0; g < 5; ++g)
#pragma unroll
                for (int q = 0; q < 4; ++q) acc[g][q] = 0.0f;

            const uint32_t abase = (rt * 16 + arl) * 256;
#pragma unroll
            for (int ks = 0; ks < 8; ++ks) {
                uint32_t aswz = abase + (((2 * ks + asel) ^ (arl & 7)) * 16);
                uint32_t ah[4], al[4];
                ldsm4(ah[0], ah[1], ah[2], ah[3], smu + SM_XHI + aswz);
                ldsm4(al[0], al[1], al[2], al[3], smu + SM_XLO + aswz);
#pragma unroll
                for (int g = 0; g < 5; ++g) {
                    uint32_t brow = g * 64 + ct * 8 + brl;
                    uint32_t bswz = brow * 256 + (((2 * ks + bsel) ^ brl) * 16);
                    uint32_t bw[2];
                    ldsm2(bw[0], bw[1], smu + SM_W + bswz);
                    mma16816h(acc[g], ah, bw);   // hi * w
                    mma16816h(acc[g], al, bw);   // lo * w
                }
            }

            if (vA) {
                float h0, c0, h1, c1;
                lstm1f(acc[0][0] + bi.x, acc[1][0] + bo.x, acc[2][0] + bu.x,
                       acc[3][0] + bfl.x, acc[4][0] + bfr.x, clA.x, crA.x, h0, c0);
                lstm1f(acc[0][1] + bi.y, acc[1][1] + bo.y, acc[2][1] + bu.y,
                       acc[3][1] + bfl.y, acc[4][1] + bfr.y, clA.y, crA.y, h1, c1);
                *reinterpret_cast<float2*>(h_dst + (size_t)cellA * D + d0) =
                    make_float2(h0, h1);
                *reinterpret_cast<float2*>(c_dst + (size_t)cellA * D + d0) =
                    make_float2(c0, c1);
            }
            if (vB) {
                float h0, c0, h1, c1;
                lstm1f(acc[0][2] + bi.x, acc[1][2] + bo.x, acc[2][2] + bu.x,
                       acc[3][2] + bfl.x, acc[4][2] + bfr.x, clB.x, crB.x, h0, c0);
                lstm1f(acc[0][3] + bi.y, acc[1][3] + bo.y, acc[2][3] + bu.y,
                       acc[3][3] + bfl.y, acc[4][3] + bfr.y, clB.y, crB.y, h1, c1);
                *reinterpret_cast<float2*>(h_dst + (size_t)cellB * D + d0) =
                    make_float2(h0, h1);
                *reinterpret_cast<float2*>(c_dst + (size_t)cellB * D + d0) =
                    make_float2(c0, c1);
            }
        }
        BAR_GRP(barid);   // group's X half consumed; safe to restage
    }
}

// ---- Scalar fallback merge (proven R2/R7 design), used if opt-in smem fails --
__global__ __launch_bounds__(NTH, 3)
void merge_scalar(const float* __restrict__ hb, const float* __restrict__ cb,
                  int src_sel, int dst_sel,
                  const float* __restrict__ Wl, const float* __restrict__ Wr,
                  const float* __restrict__ b,
                  int n_out, int level)
{
    const float* h_src = (src_sel == 0) ? hb : (src_sel == 1 ? g_A_h : g_B_h);
    const float* c_src = (src_sel == 0) ? cb : (src_sel == 1 ? g_A_c : g_B_c);
    float* h_dst = (dst_sel == 1) ? g_A_h : g_B_h;
    float* c_dst = (dst_sel == 1) ? g_A_c : g_B_c;

    __shared__ __align__(16) float s_buf[CPB * G5];

    const int tid   = threadIdx.x;
    const int cell0 = blockIdx.x * CPB;
    const int ct    = tid % 80;
    const int cg    = tid / 80;

    float* s_h2 = s_buf;
    {
        const float4* src4 = reinterpret_cast<const float4*>(h_src) + (size_t)cell0 * 32;
        for (int idx = tid; idx < CPB * 2 * 16; idx += NTH) {
            int r  = idx >> 4;
            int f4 = idx & 15;
            int c  = r >> 1;
            int lr = r & 1;
            float4 v = make_float4(0.f, 0.f, 0.f, 0.f);
            if (cell0 + c < n_out) v = src4[idx];
            float* dst = s_h2 + c * 128 + 8 * f4 + lr;
            dst[0] = v.x; dst[2] = v.y; dst[4] = v.z; dst[6] = v.w;
        }
    }
    __syncthreads();

    const float4* wl4 = reinterpret_cast<const float4*>(Wl);
    const float4* wr4 = reinterpret_cast<const float4*>(Wr);
    float4 b4 = reinterpret_cast<const float4*>(b)[ct];

    float acc[8][4];
#pragma unroll
    for (int c = 0; c < 8; ++c) {
        acc[c][0] = b4.x; acc[c][1] = b4.y; acc[c][2] = b4.z; acc[c][3] = b4.w;
    }
    const float4* hbase = reinterpret_cast<const float4*>(s_h2) + (cg * 8) * 32;

#pragma unroll 2
    for (int k2 = 0; k2 < 32; ++k2) {
        float4 wl0 = wl4[(2 * k2    ) * 80 + ct];
        float4 wr0 = wr4[(2 * k2    ) * 80 + ct];
        float4 wl1 = wl4[(2 * k2 + 1) * 80 + ct];
        float4 wr1 = wr4[(2 * k2 + 1) * 80 + ct];
#pragma unroll
        for (int c = 0; c < 8; ++c) {
            float4 hv = hbase[c * 32 + k2];
            float a0 = acc[c][0], a1 = acc[c][1], a2 = acc[c][2], a3 = acc[c][3];
            a0 = fmaf(wl0.x, hv.x, a0); a1 = fmaf(wl0.y, hv.x, a1);
            a2 = fmaf(wl0.z, hv.x, a2); a3 = fmaf(wl0.w, hv.x, a3);
            a0 = fmaf(wr0.x, hv.y, a0); a1 = fmaf(wr0.y, hv.y, a1);
            a2 = fmaf(wr0.z, hv.y, a2); a3 = fmaf(wr0.w, hv.y, a3);
            a0 = fmaf(wl1.x, hv.z, a0); a1 = fmaf(wl1.y, hv.z, a1);
            a2 = fmaf(wl1.z, hv.z, a2); a3 = fmaf(wl1.w, hv.z, a3);
            a0 = fmaf(wr1.x, hv.w, a0); a1 = fmaf(wr1.y, hv.w, a1);
            a2 = fmaf(wr1.z, hv.w, a2); a3 = fmaf(wr1.w, hv.w, a3);
            acc[c][0] = a0; acc[c][1] = a1; acc[c][2] = a2; acc[c][3] = a3;
        }
    }
    __syncthreads();
#pragma unroll
    for (int c = 0; c < 8; ++c) {
        float4* p = reinterpret_cast<float4*>(s_buf + (cg * 8 + c) * G5) + ct;
        *p = make_float4(acc[c][0], acc[c][1], acc[c][2], acc[c][3]);
    }
    __syncthreads();

    for (int idx = tid; idx < CPB * D; idx += NTH) {
        int c = idx >> 6;
        int d = idx & 63;
        int cell = cell0 + c;
        if (cell < n_out) {
            const float* g = s_buf + c * G5;
            float cc, hh;
            lstm1(g[d], g[D + d], g[2 * D + d], g[3 * D + d], g[4 * D + d],
                  c_src[(size_t)(2 * cell) * D + d],
                  c_src[(size_t)(2 * cell + 1) * D + d], hh, cc);
            c_dst[(size_t)cell * D + d] = cc;
            h_dst[(size_t)cell * D + d] = hh;
        }
    }

    if (blockIdx.x == 0 && tid < D) {
        int last = 2 * n_out - 1;
        g_lvl_h[level * D + tid] = h_src[(size_t)last * D + tid];
        g_lvl_c[level * D + tid] = c_src[(size_t)last * D + tid];
    }
}

// ---- Single-block tail (n <= 64) + summary fold ----
__global__ __launch_bounds__(NTH)
void tail_kernel(const float* __restrict__ mWl, const float* __restrict__ mWr,
                 const float* __restrict__ mb,
                 const float* __restrict__ sWl, const float* __restrict__ sWr,
                 const float* __restrict__ sb,
                 int n_start, int src_sel, int level_start, int n_lvls_total,
                 float* __restrict__ out)
{
    __shared__ float s_h[64 * D];
    __shared__ float s_g[8 * G5];
    __shared__ float sh[D], sc2[D];

    const int tid = threadIdx.x;
    int n = n_start, src = src_sel, level = level_start;

    while (n > 1) {
        const float* h_src = (src == 1) ? g_A_h : g_B_h;
        const float* c_src = (src == 1) ? g_A_c : g_B_c;
        int dst = (level & 1) ? 2 : 1;
        float* h_dst = (dst == 1) ? g_A_h : g_B_h;
        float* c_dst = (dst == 1) ? g_A_c : g_B_c;

        if (tid < D) {
            g_lvl_h[level * D + tid] = h_src[(n - 1) * D + tid];
            g_lvl_c[level * D + tid] = c_src[(n - 1) * D + tid];
        }
        for (int i = tid; i < n * D; i += NTH) s_h[i] = h_src[i];
        __syncthreads();

        int n_out = n >> 1;
        for (int c0 = 0; c0 < n_out; c0 += 8) {
            float acc[8];
            float bv = mb[tid];
#pragma unroll
            for (int c = 0; c < 8; ++c) acc[c] = bv;
            for (int k = 0; k < D; ++k) {
                float wlv = mWl[k * G5 + tid];
                float wrv = mWr[k * G5 + tid];
#pragma unroll
                for (int c = 0; c < 8; ++c) {
                    int cell = c0 + c;
                    if (cell < n_out) {
                        acc[c] = fmaf(s_h[(2 * cell) * D + k], wlv, acc[c]);
                        acc[c] = fmaf(s_h[(2 * cell + 1) * D + k], wrv, acc[c]);
                    }
                }
            }
#pragma unroll
            for (int c = 0; c < 8; ++c) s_g[c * G5 + tid] = acc[c];
            __syncthreads();
            for (int idx = tid; idx < 8 * D; idx += NTH) {
                int c = idx >> 6;
                int d = idx & 63;
                int cell = c0 + c;
                if (cell < n_out) {
                    const float* g = s_g + c * G5;
                    float cc = sigf(g[d]) * tanhf(g[2 * D + d])
                             + sigf(g[3 * D + d]) * c_src[(2 * cell) * D + d]
                             + sigf(g[4 * D + d]) * c_src[(2 * cell + 1) * D + d];
                    float hh = sigf(g[D + d]) * tanhf(cc);
                    c_dst[cell * D + d] = cc;
                    h_dst[cell * D + d] = hh;
                }
            }
            __syncthreads();
        }
        n = n_out; src = dst; ++level;
    }

    {
        const float* rh = (src == 1) ? g_A_h : g_B_h;
        const float* rc = (src == 1) ? g_A_c : g_B_c;
        if (tid < D) { sh[tid] = rh[tid]; sc2[tid] = rc[tid]; }
        __syncthreads();

        for (int l = n_lvls_total - 1; l >= 0; --l) {
            const float* lh = g_lvl_h + l * D;
            float acc = sb[tid];
#pragma unroll 8
            for (int k = 0; k < D; ++k) {
                acc = fmaf(sh[k], sWl[k * G5 + tid], acc);
                acc = fmaf(lh[k], sWr[k * G5 + tid], acc);
            }
            s_g[tid] = acc;
            __syncthreads();
            if (tid < D) {
                const float* lc = g_lvl_c + l * D;
                float cc = sigf(s_g[tid]) * tanhf(s_g[2 * D + tid])
                         + sigf(s_g[3 * D + tid]) * sc2[tid]
                         + sigf(s_g[4 * D + tid]) * lc[tid];
                float hh = sigf(s_g[D + tid]) * tanhf(cc);
                sc2[tid] = cc;
                sh[tid] = hh;
            }
            __syncthreads();
        }
        if (tid < D) {
            out[tid]     = sh[tid];
            out[D + tid] = sc2[tid];
        }
    }
}

extern "C" void kernel_launch(void* const* d_in, const int* in_sizes, int n_in,
                              void* d_out, int out_size)
{
    const float* h_bot = (const float*)d_in[0];
    const float* c_bot = (const float*)d_in[1];
    const float* mWl   = (const float*)d_in[2];
    const float* mWr   = (const float*)d_in[3];
    const float* mb    = (const float*)d_in[4];
    const float* sWl   = (const float*)d_in[5];
    const float* sWr   = (const float*)d_in[6];
    const float* sb    = (const float*)d_in[7];

    cudaError_t attr_ok =
        cudaFuncSetAttribute(merge_mma, cudaFuncAttributeMaxDynamicSharedMemorySize,
                             SMEM_MM);
    bool use_mma = (attr_ok == cudaSuccess);

    if (use_mma) prep_w<<<(320 * 128 + 255) / 256, 256>>>(mWl, mWr);

    int n = in_sizes[0] / D;   // 524288
    int level = 0;
    int src_sel = 0;
    while (n >= 128) {
        int n_out = n >> 1;
        int dst_sel = (level & 1) ? 2 : 1;
        if (use_mma) {
            int tiles = (n_out + MT - 1) / MT;
            int grid = tiles < 148 ? tiles : 148;
            merge_mma<<<grid, MMN, SMEM_MM>>>(
                h_bot, c_bot, src_sel, dst_sel, mb, n_out, level);
        } else {
            merge_scalar<<<(n_out + CPB - 1) / CPB, NTH>>>(
                h_bot, c_bot, src_sel, dst_sel, mWl, mWr, mb, n_out, level);
        }
        src_sel = dst_sel;
        n = n_out;
        ++level;
    }
    int total = level;
    for (int m = n; m > 1; m >>= 1) ++total;
    tail_kernel<<<1, NTH>>>(mWl, mWr, mb, sWl, sWr, sb,
                            n, src_sel, level, total, (float*)d_out);
}